// round 2
// baseline (speedup 1.0000x reference)
#include <cuda_runtime.h>

#define HW 65536
#define CC 256

// ---------------- scratch (device globals; reuse to keep footprint down) ----
// g_big: [0..33.5M) = q, [33.5M..67M) = k, [67M..100.6M) = v  (window layout)
//        after attention is consumed, [0..33.5M) is reused for out1 (ox+oy)
__device__ float g_big[100663296];   // 402 MB
// g_obn: attention output o (NCHW); after conv2 consumes it, reused for BN out
__device__ float g_obn[33554432];    // 134 MB
// transposed conv weights: [0..512K) wx as [c][k][o], [512K..1M) wy
__device__ float g_wt[1048576];      // 4 MB

// ---------------- kernel T: transpose conv weights [o][c][k] -> [c][k][o] ---
__global__ void wtrans_kernel(const float* __restrict__ wx,
                              const float* __restrict__ wy) {
    int e = blockIdx.x * 256 + threadIdx.x;   // 524288 total
    if (e >= 524288) return;
    int o = e >> 11;            // e / 2048
    int c = (e >> 3) & 255;
    int k = e & 7;
    g_wt[(c * 8 + k) * 256 + o] = wx[e];
    g_wt[524288 + (c * 8 + k) * 256 + o] = wy[e];
}

// ---------------- kernel A: qkv GEMM + scatter to window layout ------------
__global__ void __launch_bounds__(256) qkv_kernel(const float* __restrict__ x,
                                                  const float* __restrict__ wqkv) {
    __shared__ float Ws[16 * 64];
    __shared__ float Xs[16 * 64];
    int t = threadIdx.x;
    int p0 = blockIdx.x * 64;
    int o0 = blockIdx.y * 64;
    int b  = blockIdx.z;
    int tx = t & 15, ty = t >> 4;
    float acc[4][4] = {};
    const float* xb = x + (size_t)b * CC * HW;

    for (int c0 = 0; c0 < 256; c0 += 16) {
        int i = t >> 2, kkg = (t & 3) << 2;
        float4 wv = *(const float4*)(wqkv + (o0 + i) * 256 + c0 + kkg);
        Ws[(kkg + 0) * 64 + i] = wv.x;
        Ws[(kkg + 1) * 64 + i] = wv.y;
        Ws[(kkg + 2) * 64 + i] = wv.z;
        Ws[(kkg + 3) * 64 + i] = wv.w;
        int kk = t >> 4, j0 = (t & 15) << 2;
        *(float4*)(Xs + kk * 64 + j0) =
            *(const float4*)(xb + (size_t)(c0 + kk) * HW + p0 + j0);
        __syncthreads();
#pragma unroll
        for (int k2 = 0; k2 < 16; k2++) {
            float4 a = *(const float4*)(Ws + k2 * 64 + ty * 4);
            float4 bq = *(const float4*)(Xs + k2 * 64 + tx * 4);
            float av[4] = {a.x, a.y, a.z, a.w};
            float bv[4] = {bq.x, bq.y, bq.z, bq.w};
#pragma unroll
            for (int i2 = 0; i2 < 4; i2++)
#pragma unroll
                for (int j2 = 0; j2 < 4; j2++) acc[i2][j2] += av[i2] * bv[j2];
        }
        __syncthreads();
    }
    // scatter: o -> (qkv_sel, head h, dim dd), p -> (window, token)
#pragma unroll
    for (int oo = 0; oo < 4; oo++) {
        int o = o0 + ty * 4 + oo;
        int sel = o >> 8, ch = o & 255;
        int h = ch >> 4, dd = ch & 15;
#pragma unroll
        for (int pp = 0; pp < 4; pp++) {
            int p = p0 + tx * 4 + pp;
            int y = p >> 8, xq = p & 255;
            int win = b * 1024 + (y >> 3) * 32 + (xq >> 3);
            int tok = (y & 7) * 8 + (xq & 7);
            g_big[(size_t)sel * 33554432 +
                  (size_t)((win * 16 + h) * 64 + tok) * 16 + dd] = acc[oo][pp];
        }
    }
}

// ---------------- kernel B: window attention -------------------------------
__global__ void __launch_bounds__(64) attn_kernel(const float* __restrict__ rel_table) {
    __shared__ float ks[1024], vs[1024], bs[232];
    int t = threadIdx.x;
    int w = blockIdx.x;       // window 0..2047
    int h = blockIdx.y;       // head 0..15
    size_t base = ((size_t)(w * 16 + h)) * 1024;
    const float* gq = g_big;
    const float* gk = g_big + 33554432;
    const float* gv = g_big + 67108864;
#pragma unroll
    for (int i = 0; i < 4; i++) {
        *(float4*)(ks + t * 16 + i * 4) = *(const float4*)(gk + base + t * 16 + i * 4);
        *(float4*)(vs + t * 16 + i * 4) = *(const float4*)(gv + base + t * 16 + i * 4);
    }
    for (int r = t; r < 225; r += 64) bs[r] = rel_table[r * 16 + h];
    __syncthreads();

    float q[16];
#pragma unroll
    for (int i = 0; i < 4; i++)
        *(float4*)(q + i * 4) = *(const float4*)(gq + base + t * 16 + i * 4);
    int i1 = t >> 3, i2 = t & 7;

    float d[64];
#pragma unroll
    for (int j = 0; j < 64; j++) {
        const float4* kp = (const float4*)(ks + j * 16);
        float4 k0 = kp[0], k1 = kp[1], k2 = kp[2], k3 = kp[3];
        float s = q[0] * k0.x + q[1] * k0.y + q[2] * k0.z + q[3] * k0.w +
                  q[4] * k1.x + q[5] * k1.y + q[6] * k1.z + q[7] * k1.w +
                  q[8] * k2.x + q[9] * k2.y + q[10] * k2.z + q[11] * k2.w +
                  q[12] * k3.x + q[13] * k3.y + q[14] * k3.z + q[15] * k3.w;
        int j1 = j >> 3, j2 = j & 7;
        d[j] = 0.25f * s + bs[(i1 - j1 + 7) * 15 + (i2 - j2 + 7)];
    }
    float m = -1e30f;
#pragma unroll
    for (int j = 0; j < 64; j++) m = fmaxf(m, d[j]);
    float sum = 0.f;
#pragma unroll
    for (int j = 0; j < 64; j++) { d[j] = __expf(d[j] - m); sum += d[j]; }
    float inv = 1.0f / sum;

    float acc[16] = {};
#pragma unroll
    for (int j = 0; j < 64; j++) {
        float a = d[j] * inv;
        const float4* vp = (const float4*)(vs + j * 16);
        float4 v0 = vp[0], v1 = vp[1], v2 = vp[2], v3 = vp[3];
        acc[0] += a * v0.x;  acc[1] += a * v0.y;  acc[2] += a * v0.z;  acc[3] += a * v0.w;
        acc[4] += a * v1.x;  acc[5] += a * v1.y;  acc[6] += a * v1.z;  acc[7] += a * v1.w;
        acc[8] += a * v2.x;  acc[9] += a * v2.y;  acc[10] += a * v2.z; acc[11] += a * v2.w;
        acc[12] += a * v3.x; acc[13] += a * v3.y; acc[14] += a * v3.z; acc[15] += a * v3.w;
    }
    int b = w >> 10, wy = (w >> 5) & 31, wx = w & 31;
    int y = wy * 8 + i1, xq = wx * 8 + i2;
    size_t ob = ((size_t)(b * 256 + h * 16)) * HW + y * 256 + xq;
#pragma unroll
    for (int e = 0; e < 16; e++) g_obn[ob + (size_t)e * HW] = acc[e];
}

// ---------------- kernel C: fused ox+oy (8-tap C x C convs) ----------------
// out1[b,o,y,x] = sum_c sum_k wx[o,c,k]*P(y-3+k, x) + wy[o,c,k]*P(y, x-3+k) + biases
// P = reflect(256->254) in padded dim, 0 outside [0,257)
__global__ void __launch_bounds__(256) conv2_kernel(const float* __restrict__ bias_x,
                                                    const float* __restrict__ bias_y) {
    extern __shared__ float sm[];
    float* Sin = sm;          // [8 c][8 r][72 j]
    float* Wx  = sm + 4608;   // [8 c][8 k][64 o]
    float* Wy  = sm + 8704;
    int t = threadIdx.x;
    int x0 = blockIdx.x * 64;
    int y  = blockIdx.y;
    int z  = blockIdx.z;
    int b  = z >> 2, o0 = (z & 3) * 64;
    int tx = t & 15, ty = t >> 4;
    float acc[4][4] = {};
    const float* ob = g_obn + (size_t)b * CC * HW;

    for (int c0 = 0; c0 < 256; c0 += 8) {
        // input slab: rows y-3..y+4, cols x0-4..x0+67 with reflect/zero semantics
        for (int e = t; e < 4608; e += 256) {
            int c = e / 576;
            int rem = e - c * 576;
            int r = rem / 72;
            int j = rem - r * 72;
            int row = y - 3 + r, col = x0 - 4 + j;
            float v = 0.f;
            if (row >= 0 && row <= 256 && col >= 0 && col <= 256) {
                int rr = (row == 256) ? 254 : row;
                int cc = (col == 256) ? 254 : col;
                v = ob[(size_t)(c0 + c) * HW + rr * 256 + cc];
            }
            Sin[e] = v;
        }
        // weights: coalesced load, conflict-free store (o fastest both sides)
        int gbase = c0 * 2048 + o0;
        for (int e = t; e < 4096; e += 256) {
            int gi = gbase + (e >> 6) * 256 + (e & 63);
            Wx[e] = g_wt[gi];
            Wy[e] = g_wt[524288 + gi];
        }
        __syncthreads();

        for (int c = 0; c < 8; c++) {
            float rv[11];
#pragma unroll
            for (int u = 0; u < 11; u++) rv[u] = Sin[c * 576 + 3 * 72 + tx * 4 + 1 + u];
#pragma unroll
            for (int k = 0; k < 8; k++) {
                float4 wx4 = *(const float4*)(Wx + (c * 8 + k) * 64 + ty * 4);
                float4 wy4 = *(const float4*)(Wy + (c * 8 + k) * 64 + ty * 4);
                float4 by4 = *(const float4*)(Sin + c * 576 + k * 72 + tx * 4 + 4);
                float wxv[4] = {wx4.x, wx4.y, wx4.z, wx4.w};
                float wyv[4] = {wy4.x, wy4.y, wy4.z, wy4.w};
                float byv[4] = {by4.x, by4.y, by4.z, by4.w};
                float bxv[4] = {rv[k], rv[k + 1], rv[k + 2], rv[k + 3]};
#pragma unroll
                for (int oo = 0; oo < 4; oo++)
#pragma unroll
                    for (int xx = 0; xx < 4; xx++)
                        acc[oo][xx] += wxv[oo] * byv[xx] + wyv[oo] * bxv[xx];
            }
        }
        __syncthreads();
    }
    float* out1 = g_big;  // reuse q region
#pragma unroll
    for (int oo = 0; oo < 4; oo++) {
        int o = o0 + ty * 4 + oo;
        float bia = bias_x[o] + bias_y[o];
        float4 r;
        r.x = acc[oo][0] + bia; r.y = acc[oo][1] + bia;
        r.z = acc[oo][2] + bia; r.w = acc[oo][3] + bia;
        *(float4*)(out1 + (size_t)(b * 256 + o) * HW + y * 256 + x0 + tx * 4) = r;
    }
}

// ---------------- kernel D: depthwise 8x8 + BN -----------------------------
__global__ void __launch_bounds__(256) dwbn_kernel(const float* __restrict__ wdw,
                                                   const float* __restrict__ gamma,
                                                   const float* __restrict__ beta,
                                                   const float* __restrict__ mean,
                                                   const float* __restrict__ var) {
    __shared__ float S[39 * 40];
    __shared__ float ws[64];
    int t = threadIdx.x;
    int tile = blockIdx.x;
    int c = blockIdx.y, b = blockIdx.z;
    int y0 = (tile >> 3) * 32, x0 = (tile & 7) * 32;
    const float* in = g_big + ((size_t)(b * 256 + c)) * HW;
    for (int e = t; e < 39 * 39; e += 256) {
        int r = e / 39, j = e - r * 39;
        int row = y0 - 3 + r, col = x0 - 3 + j;
        float v = 0.f;
        if (row >= 0 && row <= 256 && col >= 0 && col <= 256) {
            int rr = (row == 256) ? 254 : row;
            int cc = (col == 256) ? 254 : col;
            v = in[rr * 256 + cc];
        }
        S[r * 40 + j] = v;
    }
    if (t < 64) ws[t] = wdw[c * 64 + t];
    __syncthreads();

    int ly = t >> 3, lx0 = (t & 7) * 4;
    float acc[4] = {};
#pragma unroll
    for (int ky = 0; ky < 8; ky++) {
        float rv[11];
#pragma unroll
        for (int u = 0; u < 11; u++) rv[u] = S[(ly + ky) * 40 + lx0 + u];
#pragma unroll
        for (int kx = 0; kx < 8; kx++) {
            float wv = ws[ky * 8 + kx];
#pragma unroll
            for (int j = 0; j < 4; j++) acc[j] += wv * rv[kx + j];
        }
    }
    float iv = rsqrtf(var[c] + 1e-5f);
    float sc = gamma[c] * iv;
    float sh = beta[c] - mean[c] * sc;
    float4 r;
    r.x = acc[0] * sc + sh; r.y = acc[1] * sc + sh;
    r.z = acc[2] * sc + sh; r.w = acc[3] * sc + sh;
    *(float4*)(g_obn + ((size_t)(b * 256 + c)) * HW + (y0 + ly) * 256 + x0 + lx0) = r;
}

// ---------------- kernel E: proj GEMM -> d_out -----------------------------
__global__ void __launch_bounds__(256) proj_kernel(const float* __restrict__ wp,
                                                   float* __restrict__ out) {
    __shared__ float Ws[16 * 64];
    __shared__ float Xs[16 * 64];
    int t = threadIdx.x;
    int p0 = blockIdx.x * 64;
    int o0 = blockIdx.y * 64;
    int b  = blockIdx.z;
    int tx = t & 15, ty = t >> 4;
    float acc[4][4] = {};
    const float* xb = g_obn + (size_t)b * CC * HW;

    for (int c0 = 0; c0 < 256; c0 += 16) {
        int i = t >> 2, kkg = (t & 3) << 2;
        float4 wv = *(const float4*)(wp + (o0 + i) * 256 + c0 + kkg);
        Ws[(kkg + 0) * 64 + i] = wv.x;
        Ws[(kkg + 1) * 64 + i] = wv.y;
        Ws[(kkg + 2) * 64 + i] = wv.z;
        Ws[(kkg + 3) * 64 + i] = wv.w;
        int kk = t >> 4, j0 = (t & 15) << 2;
        *(float4*)(Xs + kk * 64 + j0) =
            *(const float4*)(xb + (size_t)(c0 + kk) * HW + p0 + j0);
        __syncthreads();
#pragma unroll
        for (int k2 = 0; k2 < 16; k2++) {
            float4 a = *(const float4*)(Ws + k2 * 64 + ty * 4);
            float4 bq = *(const float4*)(Xs + k2 * 64 + tx * 4);
            float av[4] = {a.x, a.y, a.z, a.w};
            float bv[4] = {bq.x, bq.y, bq.z, bq.w};
#pragma unroll
            for (int i2 = 0; i2 < 4; i2++)
#pragma unroll
                for (int j2 = 0; j2 < 4; j2++) acc[i2][j2] += av[i2] * bv[j2];
        }
        __syncthreads();
    }
#pragma unroll
    for (int oo = 0; oo < 4; oo++) {
        float4 r;
        r.x = acc[oo][0]; r.y = acc[oo][1]; r.z = acc[oo][2]; r.w = acc[oo][3];
        *(float4*)(out + (size_t)(b * 256 + o0 + ty * 4 + oo) * HW + p0 + tx * 4) = r;
    }
}

// ---------------- launch ----------------------------------------------------
extern "C" void kernel_launch(void* const* d_in, const int* in_sizes, int n_in,
                              void* d_out, int out_size) {
    const float* x     = (const float*)d_in[0];
    const float* wqkv  = (const float*)d_in[1];
    const float* rel   = (const float*)d_in[2];
    const float* w_ax  = (const float*)d_in[3];
    const float* b_ax  = (const float*)d_in[4];
    const float* w_ay  = (const float*)d_in[5];
    const float* b_ay  = (const float*)d_in[6];
    const float* w_dw  = (const float*)d_in[7];
    const float* gm    = (const float*)d_in[8];
    const float* bt    = (const float*)d_in[9];
    const float* mn    = (const float*)d_in[10];
    const float* vr    = (const float*)d_in[11];
    const float* w_pr  = (const float*)d_in[12];
    float* out = (float*)d_out;

    cudaFuncSetAttribute(conv2_kernel, cudaFuncAttributeMaxDynamicSharedMemorySize, 51200);

    wtrans_kernel<<<2048, 256>>>(w_ax, w_ay);
    qkv_kernel<<<dim3(1024, 12, 2), 256>>>(x, wqkv);
    attn_kernel<<<dim3(2048, 16), 64>>>(rel);
    conv2_kernel<<<dim3(4, 256, 8), 256, 51200>>>(b_ax, b_ay);
    dwbn_kernel<<<dim3(64, 256, 2), 256>>>(w_dw, gm, bt, mn, vr);
    proj_kernel<<<dim3(1024, 4, 2), 256>>>(w_pr, out);
}

// round 6
// speedup vs baseline: 1.3055x; 1.3055x over previous
#include <cuda_runtime.h>
#include <cuda_bf16.h>
#include <cstdint>

#define HW 65536
#define CC 256

// ---------------- scratch ---------------------------------------------------
// g_big: [0..33.5M) q / later out1 ; [33.5M..67M) k ; [67M..100.6M) v
__device__ float g_big[100663296];
// g_obn: attention output o (NCHW); later BN output
__device__ float g_obn[33554432];
// pre-split conv weights, padded rows: per (mt, stage): hi[128][72] lo[128][72] bf16
__device__ __align__(16) __nv_bfloat16 g_wA[2359296];

// ---------------- helpers ---------------------------------------------------
__device__ __forceinline__ uint32_t smem_u32(const void* p) {
    uint32_t a;
    asm("{ .reg .u64 t; cvta.to.shared.u64 t, %1; cvt.u32.u64 %0, t; }" : "=r"(a) : "l"(p));
    return a;
}
__device__ __forceinline__ void ldsm4(uint32_t& r0, uint32_t& r1, uint32_t& r2, uint32_t& r3,
                                      uint32_t addr) {
    asm volatile("ldmatrix.sync.aligned.m8n8.x4.shared.b16 {%0,%1,%2,%3}, [%4];"
                 : "=r"(r0), "=r"(r1), "=r"(r2), "=r"(r3) : "r"(addr));
}
__device__ __forceinline__ void mma16816(float* c, uint32_t a0, uint32_t a1, uint32_t a2,
                                         uint32_t a3, uint32_t b0, uint32_t b1) {
    asm volatile("mma.sync.aligned.m16n8k16.row.col.f32.bf16.bf16.f32 "
                 "{%0,%1,%2,%3}, {%4,%5,%6,%7}, {%8,%9}, {%0,%1,%2,%3};"
                 : "+f"(c[0]), "+f"(c[1]), "+f"(c[2]), "+f"(c[3])
                 : "r"(a0), "r"(a1), "r"(a2), "r"(a3), "r"(b0), "r"(b1));
}

// ---------------- kernel P: pre-split conv weights into padded A tiles ------
// per (mt, stage s): A[128 o][64 k], k = c_l*16 + conv*8 + tap, rows padded to 72
__global__ void aprep_kernel(const float* __restrict__ wx, const float* __restrict__ wy) {
    int e = blockIdx.x * 256 + threadIdx.x;     // < 1048576
    if (e >= 1048576) return;
    int k = e & 63, o_l = (e >> 6) & 127, s = (e >> 13) & 63, mt = e >> 19;
    int c = 4 * s + (k >> 4);
    int conv = (k >> 3) & 1, tap = k & 7;
    int o = mt * 128 + o_l;
    float v = (conv ? wy : wx)[(o * 256 + c) * 8 + tap];
    __nv_bfloat16 h = __float2bfloat16(v);
    __nv_bfloat16 l = __float2bfloat16(v - __bfloat162float(h));
    size_t base = (size_t)(mt * 64 + s) * 18432;
    g_wA[base + o_l * 72 + k] = h;
    g_wA[base + 9216 + o_l * 72 + k] = l;
}

// ---------------- kernel A: qkv GEMM + scatter to window layout ------------
__global__ void __launch_bounds__(256) qkv_kernel(const float* __restrict__ x,
                                                  const float* __restrict__ wqkv) {
    __shared__ float Ws[16 * 64];
    __shared__ float Xs[16 * 64];
    int t = threadIdx.x;
    int p0 = blockIdx.x * 64;
    int o0 = blockIdx.y * 64;
    int b  = blockIdx.z;
    int tx = t & 15, ty = t >> 4;
    float acc[4][4] = {};
    const float* xb = x + (size_t)b * CC * HW;

    for (int c0 = 0; c0 < 256; c0 += 16) {
        int i = t >> 2, kkg = (t & 3) << 2;
        float4 wv = *(const float4*)(wqkv + (o0 + i) * 256 + c0 + kkg);
        Ws[(kkg + 0) * 64 + i] = wv.x;
        Ws[(kkg + 1) * 64 + i] = wv.y;
        Ws[(kkg + 2) * 64 + i] = wv.z;
        Ws[(kkg + 3) * 64 + i] = wv.w;
        int kk = t >> 4, j0 = (t & 15) << 2;
        *(float4*)(Xs + kk * 64 + j0) =
            *(const float4*)(xb + (size_t)(c0 + kk) * HW + p0 + j0);
        __syncthreads();
#pragma unroll
        for (int k2 = 0; k2 < 16; k2++) {
            float4 a = *(const float4*)(Ws + k2 * 64 + ty * 4);
            float4 bq = *(const float4*)(Xs + k2 * 64 + tx * 4);
            float av[4] = {a.x, a.y, a.z, a.w};
            float bv[4] = {bq.x, bq.y, bq.z, bq.w};
#pragma unroll
            for (int i2 = 0; i2 < 4; i2++)
#pragma unroll
                for (int j2 = 0; j2 < 4; j2++) acc[i2][j2] += av[i2] * bv[j2];
        }
        __syncthreads();
    }
#pragma unroll
    for (int oo = 0; oo < 4; oo++) {
        int o = o0 + ty * 4 + oo;
        int sel = o >> 8, ch = o & 255;
        int h = ch >> 4, dd = ch & 15;
#pragma unroll
        for (int pp = 0; pp < 4; pp++) {
            int p = p0 + tx * 4 + pp;
            int y = p >> 8, xq = p & 255;
            int win = b * 1024 + (y >> 3) * 32 + (xq >> 3);
            int tok = (y & 7) * 8 + (xq & 7);
            g_big[(size_t)sel * 33554432 +
                  (size_t)((win * 16 + h) * 64 + tok) * 16 + dd] = acc[oo][pp];
        }
    }
}

// ---------------- kernel B: window attention -------------------------------
__global__ void __launch_bounds__(64) attn_kernel(const float* __restrict__ rel_table) {
    __shared__ float ks[1024], vs[1024], bs[232];
    int t = threadIdx.x;
    int w = blockIdx.x;
    int h = blockIdx.y;
    size_t base = ((size_t)(w * 16 + h)) * 1024;
    const float* gq = g_big;
    const float* gk = g_big + 33554432;
    const float* gv = g_big + 67108864;
#pragma unroll
    for (int i = 0; i < 4; i++) {
        *(float4*)(ks + t * 16 + i * 4) = *(const float4*)(gk + base + t * 16 + i * 4);
        *(float4*)(vs + t * 16 + i * 4) = *(const float4*)(gv + base + t * 16 + i * 4);
    }
    for (int r = t; r < 225; r += 64) bs[r] = rel_table[r * 16 + h];
    __syncthreads();

    float q[16];
#pragma unroll
    for (int i = 0; i < 4; i++)
        *(float4*)(q + i * 4) = *(const float4*)(gq + base + t * 16 + i * 4);
    int i1 = t >> 3, i2 = t & 7;

    float d[64];
#pragma unroll
    for (int j = 0; j < 64; j++) {
        const float4* kp = (const float4*)(ks + j * 16);
        float4 k0 = kp[0], k1 = kp[1], k2 = kp[2], k3 = kp[3];
        float s = q[0] * k0.x + q[1] * k0.y + q[2] * k0.z + q[3] * k0.w +
                  q[4] * k1.x + q[5] * k1.y + q[6] * k1.z + q[7] * k1.w +
                  q[8] * k2.x + q[9] * k2.y + q[10] * k2.z + q[11] * k2.w +
                  q[12] * k3.x + q[13] * k3.y + q[14] * k3.z + q[15] * k3.w;
        int j1 = j >> 3, j2 = j & 7;
        d[j] = 0.25f * s + bs[(i1 - j1 + 7) * 15 + (i2 - j2 + 7)];
    }
    float m = -1e30f;
#pragma unroll
    for (int j = 0; j < 64; j++) m = fmaxf(m, d[j]);
    float sum = 0.f;
#pragma unroll
    for (int j = 0; j < 64; j++) { d[j] = __expf(d[j] - m); sum += d[j]; }
    float inv = 1.0f / sum;

    float acc[16] = {};
#pragma unroll
    for (int j = 0; j < 64; j++) {
        float a = d[j] * inv;
        const float4* vp = (const float4*)(vs + j * 16);
        float4 v0 = vp[0], v1 = vp[1], v2 = vp[2], v3 = vp[3];
        acc[0] += a * v0.x;  acc[1] += a * v0.y;  acc[2] += a * v0.z;  acc[3] += a * v0.w;
        acc[4] += a * v1.x;  acc[5] += a * v1.y;  acc[6] += a * v1.z;  acc[7] += a * v1.w;
        acc[8] += a * v2.x;  acc[9] += a * v2.y;  acc[10] += a * v2.z; acc[11] += a * v2.w;
        acc[12] += a * v3.x; acc[13] += a * v3.y; acc[14] += a * v3.z; acc[15] += a * v3.w;
    }
    int b = w >> 10, wy = (w >> 5) & 31, wx = w & 31;
    int y = wy * 8 + i1, xq = wx * 8 + i2;
    size_t ob = ((size_t)(b * 256 + h * 16)) * HW + y * 256 + xq;
#pragma unroll
    for (int e = 0; e < 16; e++) g_obn[ob + (size_t)e * HW] = acc[e];
}

// ---------------- kernel C: conv2 via mma.sync bf16 (split 3-pass) ---------
// grid (y=256, b=2, mt=2). Per CTA: D[128 o, 256 x], K=4096 in 64 stages of 64.
// smem: Ahi[128][72], Alo[128][72], Bhi[256][72], Blo[256][72]  (110592 B)
__device__ __forceinline__ float ldp(const float* cb, int r, int q) {
    if ((unsigned)r > 256u || (unsigned)q > 256u) return 0.f;
    return cb[((r == 256) ? 254 : r) * 256 + ((q == 256) ? 254 : q)];
}

__global__ void __launch_bounds__(256, 1) conv2_mma_kernel(const float* __restrict__ bias_x,
                                                           const float* __restrict__ bias_y) {
    extern __shared__ __align__(16) char dsm[];
    __nv_bfloat16* Asm = (__nv_bfloat16*)dsm;            // hi: [0,18432)B, lo: [18432,36864)B
    __nv_bfloat16* Bsm = (__nv_bfloat16*)(dsm + 36864);  // hi: [0,36864)B, lo: [36864,73728)B
    int t = threadIdx.x, wid = t >> 5, lane = t & 31;
    int y = blockIdx.x, b = blockIdx.y, mt = blockIdx.z;
    int wm = wid & 3, wn = wid >> 2;
    const float* ob = g_obn + (size_t)b * CC * HW;

    float acc[2][16][4];
#pragma unroll
    for (int i = 0; i < 2; i++)
#pragma unroll
        for (int j = 0; j < 16; j++)
#pragma unroll
            for (int r = 0; r < 4; r++) acc[i][j][r] = 0.f;

    // per-lane ldmatrix address components (bytes)
    uint32_t a_base = smem_u32(Asm);
    uint32_t b_base = smem_u32(Bsm);
    uint32_t a_loff = (uint32_t)((wm * 32 + (lane & 15)) * 144 + (lane >> 4) * 16);
    uint32_t b_loff = (uint32_t)(((lane & 7) + ((lane >> 4) << 3)) * 144 + ((lane >> 3) & 1) * 16);

    for (int s = 0; s < 64; s++) {
        // ---- A fill: contiguous copy of pre-split padded tile (36864 B) ----
        const float4* wsrc = (const float4*)(g_wA + (size_t)(mt * 64 + s) * 18432);
#pragma unroll
        for (int i = 0; i < 9; i++) ((float4*)Asm)[t + (i << 8)] = wsrc[t + (i << 8)];

        // ---- B fill: im2col + split-bf16, [x][k] rows padded to 72 ---------
        int c0 = 4 * s;
#pragma unroll
        for (int i = 0; i < 16; i++) {          // vertical taps: k = c_l*16 + 2rp{,+1}
            int id = t + (i << 8);
            int xq = id & 255, u = id >> 8;
            int c_l = u >> 2, rp = u & 3;
            const float* cb = ob + (size_t)(c0 + c_l) * HW;
            float v0 = ldp(cb, y - 3 + 2 * rp, xq);
            float v1 = ldp(cb, y - 2 + 2 * rp, xq);
            int idx = xq * 72 + c_l * 16 + 2 * rp;
            __nv_bfloat16 h0 = __float2bfloat16(v0), h1 = __float2bfloat16(v1);
            __nv_bfloat162 ph; ph.x = h0; ph.y = h1;
            __nv_bfloat162 pl;
            pl.x = __float2bfloat16(v0 - __bfloat162float(h0));
            pl.y = __float2bfloat16(v1 - __bfloat162float(h1));
            *(__nv_bfloat162*)(Bsm + idx) = ph;
            *(__nv_bfloat162*)(Bsm + 18432 + idx) = pl;
        }
#pragma unroll
        for (int i = 0; i < 16; i++) {          // horizontal taps: k = c_l*16+8+2tp{,+1}
            int id = t + (i << 8);
            int xq = id & 255, u = id >> 8;
            int c_l = u >> 2, tp = u & 3;
            const float* cb = ob + (size_t)(c0 + c_l) * HW;
            float v0 = ldp(cb, y, xq + 2 * tp - 3);
            float v1 = ldp(cb, y, xq + 2 * tp - 2);
            int idx = xq * 72 + c_l * 16 + 8 + 2 * tp;
            __nv_bfloat16 h0 = __float2bfloat16(v0), h1 = __float2bfloat16(v1);
            __nv_bfloat162 ph; ph.x = h0; ph.y = h1;
            __nv_bfloat162 pl;
            pl.x = __float2bfloat16(v0 - __bfloat162float(h0));
            pl.y = __float2bfloat16(v1 - __bfloat162float(h1));
            *(__nv_bfloat162*)(Bsm + idx) = ph;
            *(__nv_bfloat162*)(Bsm + 18432 + idx) = pl;
        }
        __syncthreads();

        // ---- consume: 4 K-steps x (A hi/lo frags + 8 B chunks x 12 mma) ----
#pragma unroll
        for (int kstep = 0; kstep < 4; kstep++) {
            uint32_t ah[2][4], al[2][4];
#pragma unroll
            for (int ma = 0; ma < 2; ma++) {
                uint32_t aaddr = a_base + a_loff + ma * 16 * 144 + kstep * 32;
                ldsm4(ah[ma][0], ah[ma][1], ah[ma][2], ah[ma][3], aaddr);
                ldsm4(al[ma][0], al[ma][1], al[ma][2], al[ma][3], aaddr + 18432);
            }
#pragma unroll
            for (int nc = 0; nc < 8; nc++) {
                uint32_t baddr = b_base + b_loff + (wn * 128 + nc * 16) * 144 + kstep * 32;
                uint32_t bh0, bh1, bh2, bh3, bl0, bl1, bl2, bl3;
                ldsm4(bh0, bh1, bh2, bh3, baddr);
                ldsm4(bl0, bl1, bl2, bl3, baddr + 36864);
#pragma unroll
                for (int ma = 0; ma < 2; ma++) {
                    mma16816(acc[ma][nc * 2 + 0], ah[ma][0], ah[ma][1], ah[ma][2], ah[ma][3], bh0, bh1);
                    mma16816(acc[ma][nc * 2 + 1], ah[ma][0], ah[ma][1], ah[ma][2], ah[ma][3], bh2, bh3);
                    mma16816(acc[ma][nc * 2 + 0], ah[ma][0], ah[ma][1], ah[ma][2], ah[ma][3], bl0, bl1);
                    mma16816(acc[ma][nc * 2 + 1], ah[ma][0], ah[ma][1], ah[ma][2], ah[ma][3], bl2, bl3);
                    mma16816(acc[ma][nc * 2 + 0], al[ma][0], al[ma][1], al[ma][2], al[ma][3], bh0, bh1);
                    mma16816(acc[ma][nc * 2 + 1], al[ma][0], al[ma][1], al[ma][2], al[ma][3], bh2, bh3);
                }
            }
        }
        __syncthreads();
    }

    // ---- epilogue: bias + direct float2 stores --------------------------------
    float* out1 = g_big;  // reuse q region
    int g = lane >> 2, tq = lane & 3;
#pragma unroll
    for (int ma = 0; ma < 2; ma++) {
        int o_base = mt * 128 + wm * 32 + ma * 16;
        int o0 = o_base + g, o1 = o_base + g + 8;
        float bia0 = bias_x[o0] + bias_y[o0];
        float bia1 = bias_x[o1] + bias_y[o1];
        float* r0 = out1 + (size_t)(b * 256 + o0) * HW + y * 256;
        float* r1 = out1 + (size_t)(b * 256 + o1) * HW + y * 256;
#pragma unroll
        for (int na = 0; na < 16; na++) {
            int xq = wn * 128 + na * 8 + tq * 2;
            float2 w0; w0.x = acc[ma][na][0] + bia0; w0.y = acc[ma][na][1] + bia0;
            float2 w1; w1.x = acc[ma][na][2] + bia1; w1.y = acc[ma][na][3] + bia1;
            *(float2*)(r0 + xq) = w0;
            *(float2*)(r1 + xq) = w1;
        }
    }
}

// ---------------- kernel D: depthwise 8x8 + BN -----------------------------
__global__ void __launch_bounds__(256) dwbn_kernel(const float* __restrict__ wdw,
                                                   const float* __restrict__ gamma,
                                                   const float* __restrict__ beta,
                                                   const float* __restrict__ mean,
                                                   const float* __restrict__ var) {
    __shared__ float S[39 * 40];
    __shared__ float ws[64];
    int t = threadIdx.x;
    int tile = blockIdx.x;
    int c = blockIdx.y, b = blockIdx.z;
    int y0 = (tile >> 3) * 32, x0 = (tile & 7) * 32;
    const float* in = g_big + ((size_t)(b * 256 + c)) * HW;
    for (int e = t; e < 39 * 39; e += 256) {
        int r = e / 39, j = e - r * 39;
        int row = y0 - 3 + r, col = x0 - 3 + j;
        float v = 0.f;
        if (row >= 0 && row <= 256 && col >= 0 && col <= 256) {
            int rr = (row == 256) ? 254 : row;
            int cc = (col == 256) ? 254 : col;
            v = in[rr * 256 + cc];
        }
        S[r * 40 + j] = v;
    }
    if (t < 64) ws[t] = wdw[c * 64 + t];
    __syncthreads();

    int ly = t >> 3, lx0 = (t & 7) * 4;
    float acc[4] = {};
#pragma unroll
    for (int ky = 0; ky < 8; ky++) {
        float rv[11];
#pragma unroll
        for (int u = 0; u < 11; u++) rv[u] = S[(ly + ky) * 40 + lx0 + u];
#pragma unroll
        for (int kx = 0; kx < 8; kx++) {
            float wv = ws[ky * 8 + kx];
#pragma unroll
            for (int j = 0; j < 4; j++) acc[j] += wv * rv[kx + j];
        }
    }
    float iv = rsqrtf(var[c] + 1e-5f);
    float sc = gamma[c] * iv;
    float sh = beta[c] - mean[c] * sc;
    float4 r;
    r.x = acc[0] * sc + sh; r.y = acc[1] * sc + sh;
    r.z = acc[2] * sc + sh; r.w = acc[3] * sc + sh;
    *(float4*)(g_obn + ((size_t)(b * 256 + c)) * HW + (y0 + ly) * 256 + x0 + lx0) = r;
}

// ---------------- kernel E: proj GEMM -> d_out -----------------------------
__global__ void __launch_bounds__(256) proj_kernel(const float* __restrict__ wp,
                                                   float* __restrict__ out) {
    __shared__ float Ws[16 * 64];
    __shared__ float Xs[16 * 64];
    int t = threadIdx.x;
    int p0 = blockIdx.x * 64;
    int o0 = blockIdx.y * 64;
    int b  = blockIdx.z;
    int tx = t & 15, ty = t >> 4;
    float acc[4][4] = {};
    const float* xb = g_obn + (size_t)b * CC * HW;

    for (int c0 = 0; c0 < 256; c0 += 16) {
        int i = t >> 2, kkg = (t & 3) << 2;
        float4 wv = *(const float4*)(wp + (o0 + i) * 256 + c0 + kkg);
        Ws[(kkg + 0) * 64 + i] = wv.x;
        Ws[(kkg + 1) * 64 + i] = wv.y;
        Ws[(kkg + 2) * 64 + i] = wv.z;
        Ws[(kkg + 3) * 64 + i] = wv.w;
        int kk = t >> 4, j0 = (t & 15) << 2;
        *(float4*)(Xs + kk * 64 + j0) =
            *(const float4*)(xb + (size_t)(c0 + kk) * HW + p0 + j0);
        __syncthreads();
#pragma unroll
        for (int k2 = 0; k2 < 16; k2++) {
            float4 a = *(const float4*)(Ws + k2 * 64 + ty * 4);
            float4 bq = *(const float4*)(Xs + k2 * 64 + tx * 4);
            float av[4] = {a.x, a.y, a.z, a.w};
            float bv[4] = {bq.x, bq.y, bq.z, bq.w};
#pragma unroll
            for (int i2 = 0; i2 < 4; i2++)
#pragma unroll
                for (int j2 = 0; j2 < 4; j2++) acc[i2][j2] += av[i2] * bv[j2];
        }
        __syncthreads();
    }
#pragma unroll
    for (int oo = 0; oo < 4; oo++) {
        float4 r;
        r.x = acc[oo][0]; r.y = acc[oo][1]; r.z = acc[oo][2]; r.w = acc[oo][3];
        *(float4*)(out + (size_t)(b * 256 + o0 + ty * 4 + oo) * HW + p0 + tx * 4) = r;
    }
}

// ---------------- launch ----------------------------------------------------
extern "C" void kernel_launch(void* const* d_in, const int* in_sizes, int n_in,
                              void* d_out, int out_size) {
    const float* x     = (const float*)d_in[0];
    const float* wqkv  = (const float*)d_in[1];
    const float* rel   = (const float*)d_in[2];
    const float* w_ax  = (const float*)d_in[3];
    const float* b_ax  = (const float*)d_in[4];
    const float* w_ay  = (const float*)d_in[5];
    const float* b_ay  = (const float*)d_in[6];
    const float* w_dw  = (const float*)d_in[7];
    const float* gm    = (const float*)d_in[8];
    const float* bt    = (const float*)d_in[9];
    const float* mn    = (const float*)d_in[10];
    const float* vr    = (const float*)d_in[11];
    const float* w_pr  = (const float*)d_in[12];
    float* out = (float*)d_out;

    cudaFuncSetAttribute(conv2_mma_kernel, cudaFuncAttributeMaxDynamicSharedMemorySize, 110592);

    aprep_kernel<<<4096, 256>>>(w_ax, w_ay);
    qkv_kernel<<<dim3(1024, 12, 2), 256>>>(x, wqkv);
    attn_kernel<<<dim3(2048, 16), 64>>>(rel);
    conv2_mma_kernel<<<dim3(256, 2, 2), 256, 110592>>>(b_ax, b_ay);
    dwbn_kernel<<<dim3(64, 256, 2), 256>>>(w_dw, gm, bt, mn, vr);
    proj_kernel<<<dim3(1024, 4, 2), 256>>>(w_pr, out);
}

// round 7
// speedup vs baseline: 3.1781x; 2.4344x over previous
#include <cuda_runtime.h>
#include <cuda_bf16.h>
#include <cstdint>

#define HW 65536
#define CC 256

// ---------------- scratch ---------------------------------------------------
// g_big: [0..33.5M) q / later out1 ; [33.5M..67M) k ; [67M..100.6M) v
__device__ float g_big[100663296];
// g_obn: attention output o (NCHW); later BN output
__device__ float g_obn[33554432];
// pre-split conv weights: per (mt, stage): hi[128][72] lo[128][72] bf16
__device__ __align__(16) __nv_bfloat16 g_wA[2359296];
// pre-split qkv weights: 6 mt x 4 stages
__device__ __align__(16) __nv_bfloat16 g_wQ[442368];
// pre-split proj weights: 2 mt x 4 stages
__device__ __align__(16) __nv_bfloat16 g_wP[147456];

// ---------------- helpers ---------------------------------------------------
__device__ __forceinline__ uint32_t smem_u32(const void* p) {
    uint32_t a;
    asm("{ .reg .u64 t; cvta.to.shared.u64 t, %1; cvt.u32.u64 %0, t; }" : "=r"(a) : "l"(p));
    return a;
}
__device__ __forceinline__ void ldsm4(uint32_t& r0, uint32_t& r1, uint32_t& r2, uint32_t& r3,
                                      uint32_t addr) {
    asm volatile("ldmatrix.sync.aligned.m8n8.x4.shared.b16 {%0,%1,%2,%3}, [%4];"
                 : "=r"(r0), "=r"(r1), "=r"(r2), "=r"(r3) : "r"(addr));
}
__device__ __forceinline__ void mma16816(float* c, uint32_t a0, uint32_t a1, uint32_t a2,
                                         uint32_t a3, uint32_t b0, uint32_t b1) {
    asm volatile("mma.sync.aligned.m16n8k16.row.col.f32.bf16.bf16.f32 "
                 "{%0,%1,%2,%3}, {%4,%5,%6,%7}, {%8,%9}, {%0,%1,%2,%3};"
                 : "+f"(c[0]), "+f"(c[1]), "+f"(c[2]), "+f"(c[3])
                 : "r"(a0), "r"(a1), "r"(a2), "r"(a3), "r"(b0), "r"(b1));
}
__device__ __forceinline__ void split2(float v0, float v1, __nv_bfloat162& ph, __nv_bfloat162& pl) {
    __nv_bfloat16 h0 = __float2bfloat16(v0), h1 = __float2bfloat16(v1);
    ph.x = h0; ph.y = h1;
    pl.x = __float2bfloat16(v0 - __bfloat162float(h0));
    pl.y = __float2bfloat16(v1 - __bfloat162float(h1));
}

// ---------------- weight prep kernels --------------------------------------
// conv: per (mt, stage s of 64): A[128 o][64 k], k = c_l*16 + conv*8 + tap
__global__ void aprep_kernel(const float* __restrict__ wx, const float* __restrict__ wy) {
    int e = blockIdx.x * 256 + threadIdx.x;     // < 1048576
    if (e >= 1048576) return;
    int k = e & 63, o_l = (e >> 6) & 127, s = (e >> 13) & 63, mt = e >> 19;
    int c = 4 * s + (k >> 4);
    int conv = (k >> 3) & 1, tap = k & 7;
    int o = mt * 128 + o_l;
    float v = (conv ? wy : wx)[(o * 256 + c) * 8 + tap];
    __nv_bfloat16 h = __float2bfloat16(v);
    __nv_bfloat16 l = __float2bfloat16(v - __bfloat162float(h));
    size_t base = (size_t)(mt * 64 + s) * 18432;
    g_wA[base + o_l * 72 + k] = h;
    g_wA[base + 9216 + o_l * 72 + k] = l;
}
// qkv: 6 mt x 4 stages of K=64 channels
__global__ void qprep_kernel(const float* __restrict__ wqkv) {
    int e = blockIdx.x * 256 + threadIdx.x;     // < 196608
    if (e >= 196608) return;
    int k = e & 63, o_l = (e >> 6) & 127, s = (e >> 13) & 3, mt = e >> 15;
    float v = wqkv[(mt * 128 + o_l) * 256 + s * 64 + k];
    __nv_bfloat16 h = __float2bfloat16(v);
    __nv_bfloat16 l = __float2bfloat16(v - __bfloat162float(h));
    size_t base = (size_t)(mt * 4 + s) * 18432;
    g_wQ[base + o_l * 72 + k] = h;
    g_wQ[base + 9216 + o_l * 72 + k] = l;
}
// proj: 2 mt x 4 stages
__global__ void pprep_kernel(const float* __restrict__ wp) {
    int e = blockIdx.x * 256 + threadIdx.x;     // < 65536
    int k = e & 63, o_l = (e >> 6) & 127, s = (e >> 13) & 3, mt = e >> 15;
    float v = wp[(mt * 128 + o_l) * 256 + s * 64 + k];
    __nv_bfloat16 h = __float2bfloat16(v);
    __nv_bfloat16 l = __float2bfloat16(v - __bfloat162float(h));
    size_t base = (size_t)(mt * 4 + s) * 18432;
    g_wP[base + o_l * 72 + k] = h;
    g_wP[base + 9216 + o_l * 72 + k] = l;
}

// ---------------- kernel A: qkv via mma (split-bf16 3-pass) -----------------
// grid (y=256, b=2, z=12: mt 0..5, nt 0..1). Tile: M=128 (3C rows), N=128 px of row y.
__global__ void __launch_bounds__(256, 2) qkv_mma_kernel(const float* __restrict__ x) {
    extern __shared__ __align__(16) char dsm[];
    __nv_bfloat16* Asm = (__nv_bfloat16*)dsm;            // hi [0,9216), lo [9216,18432) elems
    __nv_bfloat16* Bsm = (__nv_bfloat16*)(dsm + 36864);  // hi [0,9216), lo [9216,18432) elems
    int t = threadIdx.x, wid = t >> 5, lane = t & 31;
    int y = blockIdx.x, b = blockIdx.y, z = blockIdx.z;
    int mt = z >> 1, nt = z & 1;
    int x0 = nt * 128;
    int wm = wid & 3, wn = wid >> 2;
    const float* xb = x + (size_t)b * CC * HW;

    float acc[2][8][4];
#pragma unroll
    for (int i = 0; i < 2; i++)
#pragma unroll
        for (int j = 0; j < 8; j++)
#pragma unroll
            for (int r = 0; r < 4; r++) acc[i][j][r] = 0.f;

    uint32_t a_base = smem_u32(Asm);
    uint32_t b_base = smem_u32(Bsm);
    uint32_t a_loff = (uint32_t)((wm * 32 + (lane & 15)) * 144 + (lane >> 4) * 16);
    uint32_t b_loff = (uint32_t)(((lane & 7) + ((lane >> 4) << 3)) * 144 + ((lane >> 3) & 1) * 16);

    for (int s = 0; s < 4; s++) {
        const float4* wsrc = (const float4*)(g_wQ + (size_t)(mt * 4 + s) * 18432);
#pragma unroll
        for (int i = 0; i < 9; i++) ((float4*)Asm)[t + (i << 8)] = wsrc[t + (i << 8)];

        int c0 = s * 64;
#pragma unroll
        for (int i = 0; i < 16; i++) {          // 4096 pairs: k=2j channels, x=xl
            int id = t + (i << 8);
            int xl = id & 127, j = id >> 7;     // j in [0,32)
            const float* row = xb + (size_t)(c0 + 2 * j) * HW + y * 256 + x0;
            float v0 = row[xl];
            float v1 = row[xl + HW];
            __nv_bfloat162 ph, pl;
            split2(v0, v1, ph, pl);
            int idx = xl * 72 + 2 * j;
            *(__nv_bfloat162*)(Bsm + idx) = ph;
            *(__nv_bfloat162*)(Bsm + 9216 + idx) = pl;
        }
        __syncthreads();

#pragma unroll
        for (int kstep = 0; kstep < 4; kstep++) {
            uint32_t ah[2][4], al[2][4];
#pragma unroll
            for (int ma = 0; ma < 2; ma++) {
                uint32_t aaddr = a_base + a_loff + ma * 16 * 144 + kstep * 32;
                ldsm4(ah[ma][0], ah[ma][1], ah[ma][2], ah[ma][3], aaddr);
                ldsm4(al[ma][0], al[ma][1], al[ma][2], al[ma][3], aaddr + 18432);
            }
#pragma unroll
            for (int nc = 0; nc < 4; nc++) {
                uint32_t baddr = b_base + b_loff + (wn * 64 + nc * 16) * 144 + kstep * 32;
                uint32_t bh0, bh1, bh2, bh3, bl0, bl1, bl2, bl3;
                ldsm4(bh0, bh1, bh2, bh3, baddr);
                ldsm4(bl0, bl1, bl2, bl3, baddr + 18432);
#pragma unroll
                for (int ma = 0; ma < 2; ma++) {
                    mma16816(acc[ma][nc * 2 + 0], ah[ma][0], ah[ma][1], ah[ma][2], ah[ma][3], bh0, bh1);
                    mma16816(acc[ma][nc * 2 + 1], ah[ma][0], ah[ma][1], ah[ma][2], ah[ma][3], bh2, bh3);
                    mma16816(acc[ma][nc * 2 + 0], ah[ma][0], ah[ma][1], ah[ma][2], ah[ma][3], bl0, bl1);
                    mma16816(acc[ma][nc * 2 + 1], ah[ma][0], ah[ma][1], ah[ma][2], ah[ma][3], bl2, bl3);
                    mma16816(acc[ma][nc * 2 + 0], al[ma][0], al[ma][1], al[ma][2], al[ma][3], bh0, bh1);
                    mma16816(acc[ma][nc * 2 + 1], al[ma][0], al[ma][1], al[ma][2], al[ma][3], bh2, bh3);
                }
            }
        }
        __syncthreads();
    }

    // epilogue: scatter to window layout q/k/v
    int g = lane >> 2, tq = lane & 3;
    int win_row = b * 1024 + (y >> 3) * 32;
    int tokb = (y & 7) * 8;
#pragma unroll
    for (int ma = 0; ma < 2; ma++) {
        int o_a = mt * 128 + wm * 32 + ma * 16 + g;
        int o_b = o_a + 8;
        int sel_a = o_a >> 8, h_a = (o_a >> 4) & 15, dd_a = o_a & 15;
        int sel_b = o_b >> 8, h_b = (o_b >> 4) & 15, dd_b = o_b & 15;
#pragma unroll
        for (int na = 0; na < 8; na++) {
            int xq = x0 + wn * 64 + na * 8 + tq * 2;
            int win = win_row + (xq >> 3);
            int tok = tokb + (xq & 7);
            size_t pa = (size_t)sel_a * 33554432 + (size_t)((win * 16 + h_a) * 64 + tok) * 16 + dd_a;
            size_t pb = (size_t)sel_b * 33554432 + (size_t)((win * 16 + h_b) * 64 + tok) * 16 + dd_b;
            g_big[pa] = acc[ma][na][0];
            g_big[pa + 16] = acc[ma][na][1];
            g_big[pb] = acc[ma][na][2];
            g_big[pb + 16] = acc[ma][na][3];
        }
    }
}

// ---------------- kernel B: window attention -------------------------------
__global__ void __launch_bounds__(64) attn_kernel(const float* __restrict__ rel_table) {
    __shared__ float ks[1024], vs[1024], bs[232];
    int t = threadIdx.x;
    int w = blockIdx.x;
    int h = blockIdx.y;
    size_t base = ((size_t)(w * 16 + h)) * 1024;
    const float* gq = g_big;
    const float* gk = g_big + 33554432;
    const float* gv = g_big + 67108864;
#pragma unroll
    for (int i = 0; i < 4; i++) {
        *(float4*)(ks + t * 16 + i * 4) = *(const float4*)(gk + base + t * 16 + i * 4);
        *(float4*)(vs + t * 16 + i * 4) = *(const float4*)(gv + base + t * 16 + i * 4);
    }
    for (int r = t; r < 225; r += 64) bs[r] = rel_table[r * 16 + h];
    __syncthreads();

    float q[16];
#pragma unroll
    for (int i = 0; i < 4; i++)
        *(float4*)(q + i * 4) = *(const float4*)(gq + base + t * 16 + i * 4);
    int i1 = t >> 3, i2 = t & 7;

    float d[64];
#pragma unroll
    for (int j = 0; j < 64; j++) {
        const float4* kp = (const float4*)(ks + j * 16);
        float4 k0 = kp[0], k1 = kp[1], k2 = kp[2], k3 = kp[3];
        float s = q[0] * k0.x + q[1] * k0.y + q[2] * k0.z + q[3] * k0.w +
                  q[4] * k1.x + q[5] * k1.y + q[6] * k1.z + q[7] * k1.w +
                  q[8] * k2.x + q[9] * k2.y + q[10] * k2.z + q[11] * k2.w +
                  q[12] * k3.x + q[13] * k3.y + q[14] * k3.z + q[15] * k3.w;
        int j1 = j >> 3, j2 = j & 7;
        d[j] = 0.25f * s + bs[(i1 - j1 + 7) * 15 + (i2 - j2 + 7)];
    }
    float m = -1e30f;
#pragma unroll
    for (int j = 0; j < 64; j++) m = fmaxf(m, d[j]);
    float sum = 0.f;
#pragma unroll
    for (int j = 0; j < 64; j++) { d[j] = __expf(d[j] - m); sum += d[j]; }
    float inv = 1.0f / sum;

    float acc[16] = {};
#pragma unroll
    for (int j = 0; j < 64; j++) {
        float a = d[j] * inv;
        const float4* vp = (const float4*)(vs + j * 16);
        float4 v0 = vp[0], v1 = vp[1], v2 = vp[2], v3 = vp[3];
        acc[0] += a * v0.x;  acc[1] += a * v0.y;  acc[2] += a * v0.z;  acc[3] += a * v0.w;
        acc[4] += a * v1.x;  acc[5] += a * v1.y;  acc[6] += a * v1.z;  acc[7] += a * v1.w;
        acc[8] += a * v2.x;  acc[9] += a * v2.y;  acc[10] += a * v2.z; acc[11] += a * v2.w;
        acc[12] += a * v3.x; acc[13] += a * v3.y; acc[14] += a * v3.z; acc[15] += a * v3.w;
    }
    int b = w >> 10, wy = (w >> 5) & 31, wx = w & 31;
    int y = wy * 8 + i1, xq = wx * 8 + i2;
    size_t ob = ((size_t)(b * 256 + h * 16)) * HW + y * 256 + xq;
#pragma unroll
    for (int e = 0; e < 16; e++) g_obn[ob + (size_t)e * HW] = acc[e];
}

// ---------------- kernel C: conv2 via mma (split 3-pass, N=128, 2 CTA/SM) --
__device__ __forceinline__ float ldp(const float* cb, int r, int q) {
    if ((unsigned)r > 256u || (unsigned)q > 256u) return 0.f;
    return cb[((r == 256) ? 254 : r) * 256 + ((q == 256) ? 254 : q)];
}

__global__ void __launch_bounds__(256, 2) conv2_mma_kernel(const float* __restrict__ bias_x,
                                                           const float* __restrict__ bias_y) {
    extern __shared__ __align__(16) char dsm[];
    __nv_bfloat16* Asm = (__nv_bfloat16*)dsm;            // hi [0,9216), lo [9216,18432) elems
    __nv_bfloat16* Bsm = (__nv_bfloat16*)(dsm + 36864);
    int t = threadIdx.x, wid = t >> 5, lane = t & 31;
    int y = blockIdx.x, b = blockIdx.y, z = blockIdx.z;
    int mt = z >> 1, nt = z & 1;
    int x0 = nt * 128;
    int wm = wid & 3, wn = wid >> 2;
    const float* ob = g_obn + (size_t)b * CC * HW;

    float acc[2][8][4];
#pragma unroll
    for (int i = 0; i < 2; i++)
#pragma unroll
        for (int j = 0; j < 8; j++)
#pragma unroll
            for (int r = 0; r < 4; r++) acc[i][j][r] = 0.f;

    uint32_t a_base = smem_u32(Asm);
    uint32_t b_base = smem_u32(Bsm);
    uint32_t a_loff = (uint32_t)((wm * 32 + (lane & 15)) * 144 + (lane >> 4) * 16);
    uint32_t b_loff = (uint32_t)(((lane & 7) + ((lane >> 4) << 3)) * 144 + ((lane >> 3) & 1) * 16);

    for (int s = 0; s < 64; s++) {
        const float4* wsrc = (const float4*)(g_wA + (size_t)(mt * 64 + s) * 18432);
#pragma unroll
        for (int i = 0; i < 9; i++) ((float4*)Asm)[t + (i << 8)] = wsrc[t + (i << 8)];

        int c0 = 4 * s;
#pragma unroll
        for (int i = 0; i < 8; i++) {           // vertical taps: 2048 pairs
            int id = t + (i << 8);
            int xl = id & 127, u = id >> 7;     // u in [0,16)
            int c_l = u >> 2, rp = u & 3;
            const float* cb = ob + (size_t)(c0 + c_l) * HW;
            int xq = x0 + xl;
            float v0 = ldp(cb, y - 3 + 2 * rp, xq);
            float v1 = ldp(cb, y - 2 + 2 * rp, xq);
            __nv_bfloat162 ph, pl;
            split2(v0, v1, ph, pl);
            int idx = xl * 72 + c_l * 16 + 2 * rp;
            *(__nv_bfloat162*)(Bsm + idx) = ph;
            *(__nv_bfloat162*)(Bsm + 9216 + idx) = pl;
        }
#pragma unroll
        for (int i = 0; i < 8; i++) {           // horizontal taps: 2048 pairs
            int id = t + (i << 8);
            int xl = id & 127, u = id >> 7;
            int c_l = u >> 2, tp = u & 3;
            const float* cb = ob + (size_t)(c0 + c_l) * HW;
            int xq = x0 + xl;
            float v0 = ldp(cb, y, xq + 2 * tp - 3);
            float v1 = ldp(cb, y, xq + 2 * tp - 2);
            __nv_bfloat162 ph, pl;
            split2(v0, v1, ph, pl);
            int idx = xl * 72 + c_l * 16 + 8 + 2 * tp;
            *(__nv_bfloat162*)(Bsm + idx) = ph;
            *(__nv_bfloat162*)(Bsm + 9216 + idx) = pl;
        }
        __syncthreads();

#pragma unroll
        for (int kstep = 0; kstep < 4; kstep++) {
            uint32_t ah[2][4], al[2][4];
#pragma unroll
            for (int ma = 0; ma < 2; ma++) {
                uint32_t aaddr = a_base + a_loff + ma * 16 * 144 + kstep * 32;
                ldsm4(ah[ma][0], ah[ma][1], ah[ma][2], ah[ma][3], aaddr);
                ldsm4(al[ma][0], al[ma][1], al[ma][2], al[ma][3], aaddr + 18432);
            }
#pragma unroll
            for (int nc = 0; nc < 4; nc++) {
                uint32_t baddr = b_base + b_loff + (wn * 64 + nc * 16) * 144 + kstep * 32;
                uint32_t bh0, bh1, bh2, bh3, bl0, bl1, bl2, bl3;
                ldsm4(bh0, bh1, bh2, bh3, baddr);
                ldsm4(bl0, bl1, bl2, bl3, baddr + 18432);
#pragma unroll
                for (int ma = 0; ma < 2; ma++) {
                    mma16816(acc[ma][nc * 2 + 0], ah[ma][0], ah[ma][1], ah[ma][2], ah[ma][3], bh0, bh1);
                    mma16816(acc[ma][nc * 2 + 1], ah[ma][0], ah[ma][1], ah[ma][2], ah[ma][3], bh2, bh3);
                    mma16816(acc[ma][nc * 2 + 0], ah[ma][0], ah[ma][1], ah[ma][2], ah[ma][3], bl0, bl1);
                    mma16816(acc[ma][nc * 2 + 1], ah[ma][0], ah[ma][1], ah[ma][2], ah[ma][3], bl2, bl3);
                    mma16816(acc[ma][nc * 2 + 0], al[ma][0], al[ma][1], al[ma][2], al[ma][3], bh0, bh1);
                    mma16816(acc[ma][nc * 2 + 1], al[ma][0], al[ma][1], al[ma][2], al[ma][3], bh2, bh3);
                }
            }
        }
        __syncthreads();
    }

    // epilogue: bias + float2 stores
    float* out1 = g_big;  // reuse q region
    int g = lane >> 2, tq = lane & 3;
#pragma unroll
    for (int ma = 0; ma < 2; ma++) {
        int o_base = mt * 128 + wm * 32 + ma * 16;
        int o0 = o_base + g, o1 = o_base + g + 8;
        float bia0 = bias_x[o0] + bias_y[o0];
        float bia1 = bias_x[o1] + bias_y[o1];
        float* r0 = out1 + (size_t)(b * 256 + o0) * HW + y * 256;
        float* r1 = out1 + (size_t)(b * 256 + o1) * HW + y * 256;
#pragma unroll
        for (int na = 0; na < 8; na++) {
            int xq = x0 + wn * 64 + na * 8 + tq * 2;
            float2 w0; w0.x = acc[ma][na][0] + bia0; w0.y = acc[ma][na][1] + bia0;
            float2 w1; w1.x = acc[ma][na][2] + bia1; w1.y = acc[ma][na][3] + bia1;
            *(float2*)(r0 + xq) = w0;
            *(float2*)(r1 + xq) = w1;
        }
    }
}

// ---------------- kernel D: depthwise 8x8 + BN -----------------------------
__global__ void __launch_bounds__(256) dwbn_kernel(const float* __restrict__ wdw,
                                                   const float* __restrict__ gamma,
                                                   const float* __restrict__ beta,
                                                   const float* __restrict__ mean,
                                                   const float* __restrict__ var) {
    __shared__ float S[39 * 40];
    __shared__ float ws[64];
    int t = threadIdx.x;
    int tile = blockIdx.x;
    int c = blockIdx.y, b = blockIdx.z;
    int y0 = (tile >> 3) * 32, x0 = (tile & 7) * 32;
    const float* in = g_big + ((size_t)(b * 256 + c)) * HW;
    for (int e = t; e < 39 * 39; e += 256) {
        int r = e / 39, j = e - r * 39;
        int row = y0 - 3 + r, col = x0 - 3 + j;
        float v = 0.f;
        if (row >= 0 && row <= 256 && col >= 0 && col <= 256) {
            int rr = (row == 256) ? 254 : row;
            int cc = (col == 256) ? 254 : col;
            v = in[rr * 256 + cc];
        }
        S[r * 40 + j] = v;
    }
    if (t < 64) ws[t] = wdw[c * 64 + t];
    __syncthreads();

    int ly = t >> 3, lx0 = (t & 7) * 4;
    float acc[4] = {};
#pragma unroll
    for (int ky = 0; ky < 8; ky++) {
        float rv[11];
#pragma unroll
        for (int u = 0; u < 11; u++) rv[u] = S[(ly + ky) * 40 + lx0 + u];
#pragma unroll
        for (int kx = 0; kx < 8; kx++) {
            float wv = ws[ky * 8 + kx];
#pragma unroll
            for (int j = 0; j < 4; j++) acc[j] += wv * rv[kx + j];
        }
    }
    float iv = rsqrtf(var[c] + 1e-5f);
    float sc = gamma[c] * iv;
    float sh = beta[c] - mean[c] * sc;
    float4 r;
    r.x = acc[0] * sc + sh; r.y = acc[1] * sc + sh;
    r.z = acc[2] * sc + sh; r.w = acc[3] * sc + sh;
    *(float4*)(g_obn + ((size_t)(b * 256 + c)) * HW + (y0 + ly) * 256 + x0 + lx0) = r;
}

// ---------------- kernel E: proj via mma -> d_out ---------------------------
__global__ void __launch_bounds__(256, 2) proj_mma_kernel(float* __restrict__ out) {
    extern __shared__ __align__(16) char dsm[];
    __nv_bfloat16* Asm = (__nv_bfloat16*)dsm;
    __nv_bfloat16* Bsm = (__nv_bfloat16*)(dsm + 36864);
    int t = threadIdx.x, wid = t >> 5, lane = t & 31;
    int y = blockIdx.x, b = blockIdx.y, z = blockIdx.z;
    int mt = z >> 1, nt = z & 1;
    int x0 = nt * 128;
    int wm = wid & 3, wn = wid >> 2;
    const float* xb = g_obn + (size_t)b * CC * HW;

    float acc[2][8][4];
#pragma unroll
    for (int i = 0; i < 2; i++)
#pragma unroll
        for (int j = 0; j < 8; j++)
#pragma unroll
            for (int r = 0; r < 4; r++) acc[i][j][r] = 0.f;

    uint32_t a_base = smem_u32(Asm);
    uint32_t b_base = smem_u32(Bsm);
    uint32_t a_loff = (uint32_t)((wm * 32 + (lane & 15)) * 144 + (lane >> 4) * 16);
    uint32_t b_loff = (uint32_t)(((lane & 7) + ((lane >> 4) << 3)) * 144 + ((lane >> 3) & 1) * 16);

    for (int s = 0; s < 4; s++) {
        const float4* wsrc = (const float4*)(g_wP + (size_t)(mt * 4 + s) * 18432);
#pragma unroll
        for (int i = 0; i < 9; i++) ((float4*)Asm)[t + (i << 8)] = wsrc[t + (i << 8)];

        int c0 = s * 64;
#pragma unroll
        for (int i = 0; i < 16; i++) {
            int id = t + (i << 8);
            int xl = id & 127, j = id >> 7;
            const float* row = xb + (size_t)(c0 + 2 * j) * HW + y * 256 + x0;
            float v0 = row[xl];
            float v1 = row[xl + HW];
            __nv_bfloat162 ph, pl;
            split2(v0, v1, ph, pl);
            int idx = xl * 72 + 2 * j;
            *(__nv_bfloat162*)(Bsm + idx) = ph;
            *(__nv_bfloat162*)(Bsm + 9216 + idx) = pl;
        }
        __syncthreads();

#pragma unroll
        for (int kstep = 0; kstep < 4; kstep++) {
            uint32_t ah[2][4], al[2][4];
#pragma unroll
            for (int ma = 0; ma < 2; ma++) {
                uint32_t aaddr = a_base + a_loff + ma * 16 * 144 + kstep * 32;
                ldsm4(ah[ma][0], ah[ma][1], ah[ma][2], ah[ma][3], aaddr);
                ldsm4(al[ma][0], al[ma][1], al[ma][2], al[ma][3], aaddr + 18432);
            }
#pragma unroll
            for (int nc = 0; nc < 4; nc++) {
                uint32_t baddr = b_base + b_loff + (wn * 64 + nc * 16) * 144 + kstep * 32;
                uint32_t bh0, bh1, bh2, bh3, bl0, bl1, bl2, bl3;
                ldsm4(bh0, bh1, bh2, bh3, baddr);
                ldsm4(bl0, bl1, bl2, bl3, baddr + 18432);
#pragma unroll
                for (int ma = 0; ma < 2; ma++) {
                    mma16816(acc[ma][nc * 2 + 0], ah[ma][0], ah[ma][1], ah[ma][2], ah[ma][3], bh0, bh1);
                    mma16816(acc[ma][nc * 2 + 1], ah[ma][0], ah[ma][1], ah[ma][2], ah[ma][3], bh2, bh3);
                    mma16816(acc[ma][nc * 2 + 0], ah[ma][0], ah[ma][1], ah[ma][2], ah[ma][3], bl0, bl1);
                    mma16816(acc[ma][nc * 2 + 1], ah[ma][0], ah[ma][1], ah[ma][2], ah[ma][3], bl2, bl3);
                    mma16816(acc[ma][nc * 2 + 0], al[ma][0], al[ma][1], al[ma][2], al[ma][3], bh0, bh1);
                    mma16816(acc[ma][nc * 2 + 1], al[ma][0], al[ma][1], al[ma][2], al[ma][3], bh2, bh3);
                }
            }
        }
        __syncthreads();
    }

    int g = lane >> 2, tq = lane & 3;
#pragma unroll
    for (int ma = 0; ma < 2; ma++) {
        int o_base = mt * 128 + wm * 32 + ma * 16;
        int o0 = o_base + g, o1 = o_base + g + 8;
        float* r0 = out + (size_t)(b * 256 + o0) * HW + y * 256;
        float* r1 = out + (size_t)(b * 256 + o1) * HW + y * 256;
#pragma unroll
        for (int na = 0; na < 8; na++) {
            int xq = x0 + wn * 64 + na * 8 + tq * 2;
            float2 w0; w0.x = acc[ma][na][0]; w0.y = acc[ma][na][1];
            float2 w1; w1.x = acc[ma][na][2]; w1.y = acc[ma][na][3];
            *(float2*)(r0 + xq) = w0;
            *(float2*)(r1 + xq) = w1;
        }
    }
}

// ---------------- launch ----------------------------------------------------
extern "C" void kernel_launch(void* const* d_in, const int* in_sizes, int n_in,
                              void* d_out, int out_size) {
    const float* x     = (const float*)d_in[0];
    const float* wqkv  = (const float*)d_in[1];
    const float* rel   = (const float*)d_in[2];
    const float* w_ax  = (const float*)d_in[3];
    const float* b_ax  = (const float*)d_in[4];
    const float* w_ay  = (const float*)d_in[5];
    const float* b_ay  = (const float*)d_in[6];
    const float* w_dw  = (const float*)d_in[7];
    const float* gm    = (const float*)d_in[8];
    const float* bt    = (const float*)d_in[9];
    const float* mn    = (const float*)d_in[10];
    const float* vr    = (const float*)d_in[11];
    const float* w_pr  = (const float*)d_in[12];
    float* out = (float*)d_out;

    cudaFuncSetAttribute(conv2_mma_kernel, cudaFuncAttributeMaxDynamicSharedMemorySize, 73728);
    cudaFuncSetAttribute(qkv_mma_kernel, cudaFuncAttributeMaxDynamicSharedMemorySize, 73728);
    cudaFuncSetAttribute(proj_mma_kernel, cudaFuncAttributeMaxDynamicSharedMemorySize, 73728);

    aprep_kernel<<<4096, 256>>>(w_ax, w_ay);
    qprep_kernel<<<768, 256>>>(wqkv);
    pprep_kernel<<<256, 256>>>(w_pr);
    qkv_mma_kernel<<<dim3(256, 2, 12), 256, 73728>>>(x);
    attn_kernel<<<dim3(2048, 16), 64>>>(rel);
    conv2_mma_kernel<<<dim3(256, 2, 4), 256, 73728>>>(b_ax, b_ay);
    dwbn_kernel<<<dim3(64, 256, 2), 256>>>(w_dw, gm, bt, mn, vr);
    proj_mma_kernel<<<dim3(256, 2, 4), 256, 73728>>>(out);
}

// round 8
// speedup vs baseline: 3.2265x; 1.0152x over previous
#include <cuda_runtime.h>
#include <cuda_bf16.h>
#include <cstdint>

#define HW 65536
#define CC 256

// ---------------- scratch ---------------------------------------------------
// g_big: [0..33.5M) q / later out1 ; [33.5M..67M) k ; [67M..100.6M) v
__device__ float g_big[100663296];
// g_obn: attn writes split bf16 planes (hi [0,33.5M) bf16, lo [33.5M,67M) bf16);
//        dwbn later overwrites with channel-paired split planes for proj
__device__ float g_obn[33554432];
// pre-split conv weights: per (mt, stage): hi[128][72] lo[128][72] bf16
__device__ __align__(16) __nv_bfloat16 g_wA[2359296];
// pre-split qkv weights: 6 mt x 4 stages
__device__ __align__(16) __nv_bfloat16 g_wQ[442368];
// pre-split proj weights: 2 mt x 4 stages
__device__ __align__(16) __nv_bfloat16 g_wP[147456];
// pre-split input x, channel-paired: hi pairs [0,16.7M), lo pairs [16.7M,33.5M) bf16x2
__device__ __align__(16) __nv_bfloat16 g_xsplit[67108864];

// ---------------- helpers ---------------------------------------------------
__device__ __forceinline__ uint32_t smem_u32(const void* p) {
    uint32_t a;
    asm("{ .reg .u64 t; cvta.to.shared.u64 t, %1; cvt.u32.u64 %0, t; }" : "=r"(a) : "l"(p));
    return a;
}
__device__ __forceinline__ void ldsm4(uint32_t& r0, uint32_t& r1, uint32_t& r2, uint32_t& r3,
                                      uint32_t addr) {
    asm volatile("ldmatrix.sync.aligned.m8n8.x4.shared.b16 {%0,%1,%2,%3}, [%4];"
                 : "=r"(r0), "=r"(r1), "=r"(r2), "=r"(r3) : "r"(addr));
}
__device__ __forceinline__ void mma16816(float* c, uint32_t a0, uint32_t a1, uint32_t a2,
                                         uint32_t a3, uint32_t b0, uint32_t b1) {
    asm volatile("mma.sync.aligned.m16n8k16.row.col.f32.bf16.bf16.f32 "
                 "{%0,%1,%2,%3}, {%4,%5,%6,%7}, {%8,%9}, {%0,%1,%2,%3};"
                 : "+f"(c[0]), "+f"(c[1]), "+f"(c[2]), "+f"(c[3])
                 : "r"(a0), "r"(a1), "r"(a2), "r"(a3), "r"(b0), "r"(b1));
}
__device__ __forceinline__ void split2(float v0, float v1, __nv_bfloat162& ph, __nv_bfloat162& pl) {
    __nv_bfloat16 h0 = __float2bfloat16(v0), h1 = __float2bfloat16(v1);
    ph.x = h0; ph.y = h1;
    pl.x = __float2bfloat16(v0 - __bfloat162float(h0));
    pl.y = __float2bfloat16(v1 - __bfloat162float(h1));
}
__device__ __forceinline__ void cpa16(uint32_t dst, const void* src) {
    asm volatile("cp.async.cg.shared.global [%0], [%1], 16;" :: "r"(dst), "l"(src));
}
__device__ __forceinline__ void cpa_wait() {
    asm volatile("cp.async.commit_group;");
    asm volatile("cp.async.wait_group 0;" ::: "memory");
}

// ---------------- weight/input prep kernels --------------------------------
__global__ void aprep_kernel(const float* __restrict__ wx, const float* __restrict__ wy) {
    int e = blockIdx.x * 256 + threadIdx.x;     // < 1048576
    if (e >= 1048576) return;
    int k = e & 63, o_l = (e >> 6) & 127, s = (e >> 13) & 63, mt = e >> 19;
    int c = 4 * s + (k >> 4);
    int conv = (k >> 3) & 1, tap = k & 7;
    int o = mt * 128 + o_l;
    float v = (conv ? wy : wx)[(o * 256 + c) * 8 + tap];
    __nv_bfloat16 h = __float2bfloat16(v);
    __nv_bfloat16 l = __float2bfloat16(v - __bfloat162float(h));
    size_t base = (size_t)(mt * 64 + s) * 18432;
    g_wA[base + o_l * 72 + k] = h;
    g_wA[base + 9216 + o_l * 72 + k] = l;
}
__global__ void qprep_kernel(const float* __restrict__ wqkv) {
    int e = blockIdx.x * 256 + threadIdx.x;     // < 196608
    if (e >= 196608) return;
    int k = e & 63, o_l = (e >> 6) & 127, s = (e >> 13) & 3, mt = e >> 15;
    float v = wqkv[(mt * 128 + o_l) * 256 + s * 64 + k];
    __nv_bfloat16 h = __float2bfloat16(v);
    __nv_bfloat16 l = __float2bfloat16(v - __bfloat162float(h));
    size_t base = (size_t)(mt * 4 + s) * 18432;
    g_wQ[base + o_l * 72 + k] = h;
    g_wQ[base + 9216 + o_l * 72 + k] = l;
}
__global__ void pprep_kernel(const float* __restrict__ wp) {
    int e = blockIdx.x * 256 + threadIdx.x;     // < 65536
    int k = e & 63, o_l = (e >> 6) & 127, s = (e >> 13) & 3, mt = e >> 15;
    float v = wp[(mt * 128 + o_l) * 256 + s * 64 + k];
    __nv_bfloat16 h = __float2bfloat16(v);
    __nv_bfloat16 l = __float2bfloat16(v - __bfloat162float(h));
    size_t base = (size_t)(mt * 4 + s) * 18432;
    g_wP[base + o_l * 72 + k] = h;
    g_wP[base + 9216 + o_l * 72 + k] = l;
}
// x -> channel-paired split planes: pair g = (b*128+cp)*HW + pos, .x=ch 2cp, .y=ch 2cp+1
__global__ void xprep_kernel(const float* __restrict__ x) {
    int g = blockIdx.x * 256 + threadIdx.x;     // < 16777216
    int pos = g & (HW - 1);
    int cpb = g >> 16;
    const float* src = x + (size_t)(2 * cpb) * HW + pos;
    float v0 = src[0], v1 = src[HW];
    __nv_bfloat162 h, l;
    split2(v0, v1, h, l);
    ((__nv_bfloat162*)g_xsplit)[g] = h;
    ((__nv_bfloat162*)g_xsplit)[g + 16777216] = l;
}

// ---------------- kernel A: qkv via mma (split-bf16 3-pass) -----------------
__global__ void __launch_bounds__(256, 2) qkv_mma_kernel() {
    extern __shared__ __align__(16) char dsm[];
    __nv_bfloat16* Asm = (__nv_bfloat16*)dsm;
    __nv_bfloat16* Bsm = (__nv_bfloat16*)(dsm + 36864);
    int t = threadIdx.x, wid = t >> 5, lane = t & 31;
    int y = blockIdx.x, b = blockIdx.y, z = blockIdx.z;
    int mt = z >> 1, nt = z & 1;
    int x0 = nt * 128;
    int wm = wid & 3, wn = wid >> 2;

    float acc[2][8][4];
#pragma unroll
    for (int i = 0; i < 2; i++)
#pragma unroll
        for (int j = 0; j < 8; j++)
#pragma unroll
            for (int r = 0; r < 4; r++) acc[i][j][r] = 0.f;

    uint32_t a_base = smem_u32(Asm);
    uint32_t b_base = smem_u32(Bsm);
    uint32_t a_loff = (uint32_t)((wm * 32 + (lane & 15)) * 144 + (lane >> 4) * 16);
    uint32_t b_loff = (uint32_t)(((lane & 7) + ((lane >> 4) << 3)) * 144 + ((lane >> 3) & 1) * 16);

    const __nv_bfloat162* xph = (const __nv_bfloat162*)g_xsplit;
    const __nv_bfloat162* xpl = xph + 16777216;
    size_t rowb = (size_t)(b * 128) * HW + y * 256 + x0;

    for (int s = 0; s < 4; s++) {
        const float4* wsrc = (const float4*)(g_wQ + (size_t)(mt * 4 + s) * 18432);
#pragma unroll
        for (int i = 0; i < 9; i++) cpa16(a_base + (t + (i << 8)) * 16, wsrc + t + (i << 8));

        int cp0 = s * 32;
#pragma unroll
        for (int i = 0; i < 16; i++) {
            int id = t + (i << 8);
            int xl = id & 127, j = id >> 7;
            size_t g = rowb + (size_t)(cp0 + j) * HW + xl;
            int idx = xl * 72 + 2 * j;
            *(__nv_bfloat162*)(Bsm + idx) = xph[g];
            *(__nv_bfloat162*)(Bsm + 9216 + idx) = xpl[g];
        }
        cpa_wait();
        __syncthreads();

#pragma unroll
        for (int kstep = 0; kstep < 4; kstep++) {
            uint32_t ah[2][4], al[2][4];
#pragma unroll
            for (int ma = 0; ma < 2; ma++) {
                uint32_t aaddr = a_base + a_loff + ma * 16 * 144 + kstep * 32;
                ldsm4(ah[ma][0], ah[ma][1], ah[ma][2], ah[ma][3], aaddr);
                ldsm4(al[ma][0], al[ma][1], al[ma][2], al[ma][3], aaddr + 18432);
            }
#pragma unroll
            for (int nc = 0; nc < 4; nc++) {
                uint32_t baddr = b_base + b_loff + (wn * 64 + nc * 16) * 144 + kstep * 32;
                uint32_t bh0, bh1, bh2, bh3, bl0, bl1, bl2, bl3;
                ldsm4(bh0, bh1, bh2, bh3, baddr);
                ldsm4(bl0, bl1, bl2, bl3, baddr + 18432);
#pragma unroll
                for (int ma = 0; ma < 2; ma++) {
                    mma16816(acc[ma][nc * 2 + 0], ah[ma][0], ah[ma][1], ah[ma][2], ah[ma][3], bh0, bh1);
                    mma16816(acc[ma][nc * 2 + 1], ah[ma][0], ah[ma][1], ah[ma][2], ah[ma][3], bh2, bh3);
                    mma16816(acc[ma][nc * 2 + 0], ah[ma][0], ah[ma][1], ah[ma][2], ah[ma][3], bl0, bl1);
                    mma16816(acc[ma][nc * 2 + 1], ah[ma][0], ah[ma][1], ah[ma][2], ah[ma][3], bl2, bl3);
                    mma16816(acc[ma][nc * 2 + 0], al[ma][0], al[ma][1], al[ma][2], al[ma][3], bh0, bh1);
                    mma16816(acc[ma][nc * 2 + 1], al[ma][0], al[ma][1], al[ma][2], al[ma][3], bh2, bh3);
                }
            }
        }
        __syncthreads();
    }

    // epilogue: scatter to window layout q/k/v
    int g = lane >> 2, tq = lane & 3;
    int win_row = b * 1024 + (y >> 3) * 32;
    int tokb = (y & 7) * 8;
#pragma unroll
    for (int ma = 0; ma < 2; ma++) {
        int o_a = mt * 128 + wm * 32 + ma * 16 + g;
        int o_b = o_a + 8;
        int sel_a = o_a >> 8, h_a = (o_a >> 4) & 15, dd_a = o_a & 15;
        int sel_b = o_b >> 8, h_b = (o_b >> 4) & 15, dd_b = o_b & 15;
#pragma unroll
        for (int na = 0; na < 8; na++) {
            int xq = x0 + wn * 64 + na * 8 + tq * 2;
            int win = win_row + (xq >> 3);
            int tok = tokb + (xq & 7);
            size_t pa = (size_t)sel_a * 33554432 + (size_t)((win * 16 + h_a) * 64 + tok) * 16 + dd_a;
            size_t pb = (size_t)sel_b * 33554432 + (size_t)((win * 16 + h_b) * 64 + tok) * 16 + dd_b;
            g_big[pa] = acc[ma][na][0];
            g_big[pa + 16] = acc[ma][na][1];
            g_big[pb] = acc[ma][na][2];
            g_big[pb + 16] = acc[ma][na][3];
        }
    }
}

// ---------------- kernel B: window attention (writes split planes) ---------
__global__ void __launch_bounds__(64) attn_kernel(const float* __restrict__ rel_table) {
    __shared__ float ks[1024], vs[1024], bs[232];
    int t = threadIdx.x;
    int w = blockIdx.x;
    int h = blockIdx.y;
    size_t base = ((size_t)(w * 16 + h)) * 1024;
    const float* gq = g_big;
    const float* gk = g_big + 33554432;
    const float* gv = g_big + 67108864;
#pragma unroll
    for (int i = 0; i < 4; i++) {
        *(float4*)(ks + t * 16 + i * 4) = *(const float4*)(gk + base + t * 16 + i * 4);
        *(float4*)(vs + t * 16 + i * 4) = *(const float4*)(gv + base + t * 16 + i * 4);
    }
    for (int r = t; r < 225; r += 64) bs[r] = rel_table[r * 16 + h];
    __syncthreads();

    float q[16];
#pragma unroll
    for (int i = 0; i < 4; i++)
        *(float4*)(q + i * 4) = *(const float4*)(gq + base + t * 16 + i * 4);
    int i1 = t >> 3, i2 = t & 7;

    float d[64];
#pragma unroll
    for (int j = 0; j < 64; j++) {
        const float4* kp = (const float4*)(ks + j * 16);
        float4 k0 = kp[0], k1 = kp[1], k2 = kp[2], k3 = kp[3];
        float s = q[0] * k0.x + q[1] * k0.y + q[2] * k0.z + q[3] * k0.w +
                  q[4] * k1.x + q[5] * k1.y + q[6] * k1.z + q[7] * k1.w +
                  q[8] * k2.x + q[9] * k2.y + q[10] * k2.z + q[11] * k2.w +
                  q[12] * k3.x + q[13] * k3.y + q[14] * k3.z + q[15] * k3.w;
        int j1 = j >> 3, j2 = j & 7;
        d[j] = 0.25f * s + bs[(i1 - j1 + 7) * 15 + (i2 - j2 + 7)];
    }
    float m = -1e30f;
#pragma unroll
    for (int j = 0; j < 64; j++) m = fmaxf(m, d[j]);
    float sum = 0.f;
#pragma unroll
    for (int j = 0; j < 64; j++) { d[j] = __expf(d[j] - m); sum += d[j]; }
    float inv = 1.0f / sum;

    float acc[16] = {};
#pragma unroll
    for (int j = 0; j < 64; j++) {
        float a = d[j] * inv;
        const float4* vp = (const float4*)(vs + j * 16);
        float4 v0 = vp[0], v1 = vp[1], v2 = vp[2], v3 = vp[3];
        acc[0] += a * v0.x;  acc[1] += a * v0.y;  acc[2] += a * v0.z;  acc[3] += a * v0.w;
        acc[4] += a * v1.x;  acc[5] += a * v1.y;  acc[6] += a * v1.z;  acc[7] += a * v1.w;
        acc[8] += a * v2.x;  acc[9] += a * v2.y;  acc[10] += a * v2.z; acc[11] += a * v2.w;
        acc[12] += a * v3.x; acc[13] += a * v3.y; acc[14] += a * v3.z; acc[15] += a * v3.w;
    }
    int b = w >> 10, wy = (w >> 5) & 31, wx = w & 31;
    int y = wy * 8 + i1, xq = wx * 8 + i2;
    __nv_bfloat16* ophi = (__nv_bfloat16*)g_obn;
    __nv_bfloat16* oplo = ophi + 33554432;
    size_t ob = ((size_t)(b * 256 + h * 16)) * HW + y * 256 + xq;
#pragma unroll
    for (int e = 0; e < 16; e++) {
        float v = acc[e];
        __nv_bfloat16 hh = __float2bfloat16(v);
        ophi[ob + (size_t)e * HW] = hh;
        oplo[ob + (size_t)e * HW] = __float2bfloat16(v - __bfloat162float(hh));
    }
}

// ---------------- kernel C: conv2 via mma (split 3-pass, N=128, 2 CTA/SM) --
__device__ __forceinline__ __nv_bfloat16 ldpb(const __nv_bfloat16* p, int r, int q) {
    if ((unsigned)r > 256u || (unsigned)q > 256u) return __float2bfloat16(0.f);
    return p[((r == 256) ? 254 : r) * 256 + ((q == 256) ? 254 : q)];
}

__global__ void __launch_bounds__(256, 2) conv2_mma_kernel(const float* __restrict__ bias_x,
                                                           const float* __restrict__ bias_y) {
    extern __shared__ __align__(16) char dsm[];
    __nv_bfloat16* Asm = (__nv_bfloat16*)dsm;
    __nv_bfloat16* Bsm = (__nv_bfloat16*)(dsm + 36864);
    int t = threadIdx.x, wid = t >> 5, lane = t & 31;
    int y = blockIdx.x, b = blockIdx.y, z = blockIdx.z;
    int mt = z >> 1, nt = z & 1;
    int x0 = nt * 128;
    int wm = wid & 3, wn = wid >> 2;
    const __nv_bfloat16* ophi = (const __nv_bfloat16*)g_obn;
    const __nv_bfloat16* oplo = ophi + 33554432;
    size_t cbase = (size_t)b * CC * HW;

    float acc[2][8][4];
#pragma unroll
    for (int i = 0; i < 2; i++)
#pragma unroll
        for (int j = 0; j < 8; j++)
#pragma unroll
            for (int r = 0; r < 4; r++) acc[i][j][r] = 0.f;

    uint32_t a_base = smem_u32(Asm);
    uint32_t b_base = smem_u32(Bsm);
    uint32_t a_loff = (uint32_t)((wm * 32 + (lane & 15)) * 144 + (lane >> 4) * 16);
    uint32_t b_loff = (uint32_t)(((lane & 7) + ((lane >> 4) << 3)) * 144 + ((lane >> 3) & 1) * 16);

    for (int s = 0; s < 64; s++) {
        const float4* wsrc = (const float4*)(g_wA + (size_t)(mt * 64 + s) * 18432);
#pragma unroll
        for (int i = 0; i < 9; i++) cpa16(a_base + (t + (i << 8)) * 16, wsrc + t + (i << 8));

        int c0 = 4 * s;
#pragma unroll
        for (int i = 0; i < 8; i++) {           // vertical taps
            int id = t + (i << 8);
            int xl = id & 127, u = id >> 7;
            int c_l = u >> 2, rp = u & 3;
            const __nv_bfloat16* chi = ophi + cbase + (size_t)(c0 + c_l) * HW;
            const __nv_bfloat16* clo = oplo + cbase + (size_t)(c0 + c_l) * HW;
            int xq = x0 + xl;
            int r0 = y - 3 + 2 * rp, r1 = r0 + 1;
            __nv_bfloat162 ph, pl;
            ph.x = ldpb(chi, r0, xq); ph.y = ldpb(chi, r1, xq);
            pl.x = ldpb(clo, r0, xq); pl.y = ldpb(clo, r1, xq);
            int idx = xl * 72 + c_l * 16 + 2 * rp;
            *(__nv_bfloat162*)(Bsm + idx) = ph;
            *(__nv_bfloat162*)(Bsm + 9216 + idx) = pl;
        }
#pragma unroll
        for (int i = 0; i < 8; i++) {           // horizontal taps
            int id = t + (i << 8);
            int xl = id & 127, u = id >> 7;
            int c_l = u >> 2, tp = u & 3;
            const __nv_bfloat16* chi = ophi + cbase + (size_t)(c0 + c_l) * HW;
            const __nv_bfloat16* clo = oplo + cbase + (size_t)(c0 + c_l) * HW;
            int xq = x0 + xl;
            int q0 = xq + 2 * tp - 3, q1 = q0 + 1;
            __nv_bfloat162 ph, pl;
            ph.x = ldpb(chi, y, q0); ph.y = ldpb(chi, y, q1);
            pl.x = ldpb(clo, y, q0); pl.y = ldpb(clo, y, q1);
            int idx = xl * 72 + c_l * 16 + 8 + 2 * tp;
            *(__nv_bfloat162*)(Bsm + idx) = ph;
            *(__nv_bfloat162*)(Bsm + 9216 + idx) = pl;
        }
        cpa_wait();
        __syncthreads();

#pragma unroll
        for (int kstep = 0; kstep < 4; kstep++) {
            uint32_t ah[2][4], al[2][4];
#pragma unroll
            for (int ma = 0; ma < 2; ma++) {
                uint32_t aaddr = a_base + a_loff + ma * 16 * 144 + kstep * 32;
                ldsm4(ah[ma][0], ah[ma][1], ah[ma][2], ah[ma][3], aaddr);
                ldsm4(al[ma][0], al[ma][1], al[ma][2], al[ma][3], aaddr + 18432);
            }
#pragma unroll
            for (int nc = 0; nc < 4; nc++) {
                uint32_t baddr = b_base + b_loff + (wn * 64 + nc * 16) * 144 + kstep * 32;
                uint32_t bh0, bh1, bh2, bh3, bl0, bl1, bl2, bl3;
                ldsm4(bh0, bh1, bh2, bh3, baddr);
                ldsm4(bl0, bl1, bl2, bl3, baddr + 18432);
#pragma unroll
                for (int ma = 0; ma < 2; ma++) {
                    mma16816(acc[ma][nc * 2 + 0], ah[ma][0], ah[ma][1], ah[ma][2], ah[ma][3], bh0, bh1);
                    mma16816(acc[ma][nc * 2 + 1], ah[ma][0], ah[ma][1], ah[ma][2], ah[ma][3], bh2, bh3);
                    mma16816(acc[ma][nc * 2 + 0], ah[ma][0], ah[ma][1], ah[ma][2], ah[ma][3], bl0, bl1);
                    mma16816(acc[ma][nc * 2 + 1], ah[ma][0], ah[ma][1], ah[ma][2], ah[ma][3], bl2, bl3);
                    mma16816(acc[ma][nc * 2 + 0], al[ma][0], al[ma][1], al[ma][2], al[ma][3], bh0, bh1);
                    mma16816(acc[ma][nc * 2 + 1], al[ma][0], al[ma][1], al[ma][2], al[ma][3], bh2, bh3);
                }
            }
        }
        __syncthreads();
    }

    // epilogue: bias + float2 stores
    float* out1 = g_big;  // reuse q region
    int g = lane >> 2, tq = lane & 3;
#pragma unroll
    for (int ma = 0; ma < 2; ma++) {
        int o_base = mt * 128 + wm * 32 + ma * 16;
        int o0 = o_base + g, o1 = o_base + g + 8;
        float bia0 = bias_x[o0] + bias_y[o0];
        float bia1 = bias_x[o1] + bias_y[o1];
        float* r0 = out1 + (size_t)(b * 256 + o0) * HW + y * 256;
        float* r1 = out1 + (size_t)(b * 256 + o1) * HW + y * 256;
#pragma unroll
        for (int na = 0; na < 8; na++) {
            int xq = x0 + wn * 64 + na * 8 + tq * 2;
            float2 w0; w0.x = acc[ma][na][0] + bia0; w0.y = acc[ma][na][1] + bia0;
            float2 w1; w1.x = acc[ma][na][2] + bia1; w1.y = acc[ma][na][3] + bia1;
            *(float2*)(r0 + xq) = w0;
            *(float2*)(r1 + xq) = w1;
        }
    }
}

// ---------------- kernel D: depthwise 8x8 + BN, channel-paired split out ---
__global__ void __launch_bounds__(256) dwbn_kernel(const float* __restrict__ wdw,
                                                   const float* __restrict__ gamma,
                                                   const float* __restrict__ beta,
                                                   const float* __restrict__ mean,
                                                   const float* __restrict__ var) {
    __shared__ float S[2][1560];
    __shared__ float ws[128];
    int t = threadIdx.x;
    int tile = blockIdx.x;
    int cp = blockIdx.y, b = blockIdx.z;
    int c0 = 2 * cp;
    int y0 = (tile >> 3) * 32, x0 = (tile & 7) * 32;
#pragma unroll
    for (int ch = 0; ch < 2; ch++) {
        const float* in = g_big + ((size_t)(b * 256 + c0 + ch)) * HW;
        for (int e = t; e < 39 * 39; e += 256) {
            int r = e / 39, j = e - r * 39;
            int row = y0 - 3 + r, col = x0 - 3 + j;
            float v = 0.f;
            if (row >= 0 && row <= 256 && col >= 0 && col <= 256) {
                int rr = (row == 256) ? 254 : row;
                int cc = (col == 256) ? 254 : col;
                v = in[rr * 256 + cc];
            }
            S[ch][r * 40 + j] = v;
        }
    }
    if (t < 128) ws[t] = wdw[c0 * 64 + t];
    __syncthreads();

    int ly = t >> 3, lx0 = (t & 7) * 4;
    float acc[2][4] = {};
#pragma unroll
    for (int ch = 0; ch < 2; ch++) {
#pragma unroll
        for (int ky = 0; ky < 8; ky++) {
            float rv[11];
#pragma unroll
            for (int u = 0; u < 11; u++) rv[u] = S[ch][(ly + ky) * 40 + lx0 + u];
#pragma unroll
            for (int kx = 0; kx < 8; kx++) {
                float wv = ws[ch * 64 + ky * 8 + kx];
#pragma unroll
                for (int j = 0; j < 4; j++) acc[ch][j] += wv * rv[kx + j];
            }
        }
    }
    float iv0 = rsqrtf(var[c0] + 1e-5f), iv1 = rsqrtf(var[c0 + 1] + 1e-5f);
    float sc0 = gamma[c0] * iv0, sc1 = gamma[c0 + 1] * iv1;
    float sh0 = beta[c0] - mean[c0] * sc0, sh1 = beta[c0 + 1] - mean[c0 + 1] * sc1;
    __nv_bfloat162* oh = (__nv_bfloat162*)g_obn;
    __nv_bfloat162* ol = oh + 16777216;
    size_t g = ((size_t)(b * 128 + cp)) * HW + (y0 + ly) * 256 + x0 + lx0;
#pragma unroll
    for (int j = 0; j < 4; j++) {
        float u0 = acc[0][j] * sc0 + sh0;
        float u1 = acc[1][j] * sc1 + sh1;
        __nv_bfloat162 hh, ll;
        split2(u0, u1, hh, ll);
        oh[g + j] = hh;
        ol[g + j] = ll;
    }
}

// ---------------- kernel E: proj via mma -> d_out ---------------------------
__global__ void __launch_bounds__(256, 2) proj_mma_kernel(float* __restrict__ out) {
    extern __shared__ __align__(16) char dsm[];
    __nv_bfloat16* Asm = (__nv_bfloat16*)dsm;
    __nv_bfloat16* Bsm = (__nv_bfloat16*)(dsm + 36864);
    int t = threadIdx.x, wid = t >> 5, lane = t & 31;
    int y = blockIdx.x, b = blockIdx.y, z = blockIdx.z;
    int mt = z >> 1, nt = z & 1;
    int x0 = nt * 128;
    int wm = wid & 3, wn = wid >> 2;

    float acc[2][8][4];
#pragma unroll
    for (int i = 0; i < 2; i++)
#pragma unroll
        for (int j = 0; j < 8; j++)
#pragma unroll
            for (int r = 0; r < 4; r++) acc[i][j][r] = 0.f;

    uint32_t a_base = smem_u32(Asm);
    uint32_t b_base = smem_u32(Bsm);
    uint32_t a_loff = (uint32_t)((wm * 32 + (lane & 15)) * 144 + (lane >> 4) * 16);
    uint32_t b_loff = (uint32_t)(((lane & 7) + ((lane >> 4) << 3)) * 144 + ((lane >> 3) & 1) * 16);

    const __nv_bfloat162* dph = (const __nv_bfloat162*)g_obn;
    const __nv_bfloat162* dpl = dph + 16777216;
    size_t rowb = (size_t)(b * 128) * HW + y * 256 + x0;

    for (int s = 0; s < 4; s++) {
        const float4* wsrc = (const float4*)(g_wP + (size_t)(mt * 4 + s) * 18432);
#pragma unroll
        for (int i = 0; i < 9; i++) cpa16(a_base + (t + (i << 8)) * 16, wsrc + t + (i << 8));

        int cp0 = s * 32;
#pragma unroll
        for (int i = 0; i < 16; i++) {
            int id = t + (i << 8);
            int xl = id & 127, j = id >> 7;
            size_t g = rowb + (size_t)(cp0 + j) * HW + xl;
            int idx = xl * 72 + 2 * j;
            *(__nv_bfloat162*)(Bsm + idx) = dph[g];
            *(__nv_bfloat162*)(Bsm + 9216 + idx) = dpl[g];
        }
        cpa_wait();
        __syncthreads();

#pragma unroll
        for (int kstep = 0; kstep < 4; kstep++) {
            uint32_t ah[2][4], al[2][4];
#pragma unroll
            for (int ma = 0; ma < 2; ma++) {
                uint32_t aaddr = a_base + a_loff + ma * 16 * 144 + kstep * 32;
                ldsm4(ah[ma][0], ah[ma][1], ah[ma][2], ah[ma][3], aaddr);
                ldsm4(al[ma][0], al[ma][1], al[ma][2], al[ma][3], aaddr + 18432);
            }
#pragma unroll
            for (int nc = 0; nc < 4; nc++) {
                uint32_t baddr = b_base + b_loff + (wn * 64 + nc * 16) * 144 + kstep * 32;
                uint32_t bh0, bh1, bh2, bh3, bl0, bl1, bl2, bl3;
                ldsm4(bh0, bh1, bh2, bh3, baddr);
                ldsm4(bl0, bl1, bl2, bl3, baddr + 18432);
#pragma unroll
                for (int ma = 0; ma < 2; ma++) {
                    mma16816(acc[ma][nc * 2 + 0], ah[ma][0], ah[ma][1], ah[ma][2], ah[ma][3], bh0, bh1);
                    mma16816(acc[ma][nc * 2 + 1], ah[ma][0], ah[ma][1], ah[ma][2], ah[ma][3], bh2, bh3);
                    mma16816(acc[ma][nc * 2 + 0], ah[ma][0], ah[ma][1], ah[ma][2], ah[ma][3], bl0, bl1);
                    mma16816(acc[ma][nc * 2 + 1], ah[ma][0], ah[ma][1], ah[ma][2], ah[ma][3], bl2, bl3);
                    mma16816(acc[ma][nc * 2 + 0], al[ma][0], al[ma][1], al[ma][2], al[ma][3], bh0, bh1);
                    mma16816(acc[ma][nc * 2 + 1], al[ma][0], al[ma][1], al[ma][2], al[ma][3], bh2, bh3);
                }
            }
        }
        __syncthreads();
    }

    int g = lane >> 2, tq = lane & 3;
#pragma unroll
    for (int ma = 0; ma < 2; ma++) {
        int o_base = mt * 128 + wm * 32 + ma * 16;
        int o0 = o_base + g, o1 = o_base + g + 8;
        float* r0 = out + (size_t)(b * 256 + o0) * HW + y * 256;
        float* r1 = out + (size_t)(b * 256 + o1) * HW + y * 256;
#pragma unroll
        for (int na = 0; na < 8; na++) {
            int xq = x0 + wn * 64 + na * 8 + tq * 2;
            float2 w0; w0.x = acc[ma][na][0]; w0.y = acc[ma][na][1];
            float2 w1; w1.x = acc[ma][na][2]; w1.y = acc[ma][na][3];
            *(float2*)(r0 + xq) = w0;
            *(float2*)(r1 + xq) = w1;
        }
    }
}

// ---------------- launch ----------------------------------------------------
extern "C" void kernel_launch(void* const* d_in, const int* in_sizes, int n_in,
                              void* d_out, int out_size) {
    const float* x     = (const float*)d_in[0];
    const float* wqkv  = (const float*)d_in[1];
    const float* rel   = (const float*)d_in[2];
    const float* w_ax  = (const float*)d_in[3];
    const float* b_ax  = (const float*)d_in[4];
    const float* w_ay  = (const float*)d_in[5];
    const float* b_ay  = (const float*)d_in[6];
    const float* w_dw  = (const float*)d_in[7];
    const float* gm    = (const float*)d_in[8];
    const float* bt    = (const float*)d_in[9];
    const float* mn    = (const float*)d_in[10];
    const float* vr    = (const float*)d_in[11];
    const float* w_pr  = (const float*)d_in[12];
    float* out = (float*)d_out;

    cudaFuncSetAttribute(conv2_mma_kernel, cudaFuncAttributeMaxDynamicSharedMemorySize, 73728);
    cudaFuncSetAttribute(qkv_mma_kernel, cudaFuncAttributeMaxDynamicSharedMemorySize, 73728);
    cudaFuncSetAttribute(proj_mma_kernel, cudaFuncAttributeMaxDynamicSharedMemorySize, 73728);

    aprep_kernel<<<4096, 256>>>(w_ax, w_ay);
    qprep_kernel<<<768, 256>>>(wqkv);
    pprep_kernel<<<256, 256>>>(w_pr);
    xprep_kernel<<<65536, 256>>>(x);
    qkv_mma_kernel<<<dim3(256, 2, 12), 256, 73728>>>();
    attn_kernel<<<dim3(2048, 16), 64>>>(rel);
    conv2_mma_kernel<<<dim3(256, 2, 4), 256, 73728>>>(b_ax, b_ay);
    dwbn_kernel<<<dim3(64, 128, 2), 256>>>(w_dw, gm, bt, mn, vr);
    proj_mma_kernel<<<dim3(256, 2, 4), 256, 73728>>>(out);
}